// round 13
// baseline (speedup 1.0000x reference)
#include <cuda_runtime.h>
#include <cuda_bf16.h>
#include <math.h>
#include <stdint.h>

// Problem constants
#define B_    16
#define N_    4096
#define C_    256
#define HEADS_ 8
#define D_    32
#define HID_  1024
#define ROWS_ 65536          // B_*N_

// ---------------- scratch (device globals; no allocation allowed) ----------
__device__ float g_xn  [ROWS_ * C_];           // norm1(x)
__device__ float g_b1  [ROWS_ * C_];           // x2
__device__ float g_b2  [ROWS_ * C_];           // x3
__device__ __nv_bfloat16 g_qkv16[ROWS_ * 3 * C_]; // qkv (bf16)
__device__ __nv_bfloat16 g_a16 [ROWS_ * C_];   // xa / attn / ln2 (bf16, reused)
__device__ __nv_bfloat16 g_h16a[ROWS_ * HID_]; // fc1 out (bf16)
__device__ __nv_bfloat16 g_h16b[ROWS_ * HID_]; // xn-bf16 shadow (early) / dwconv out (late)
__device__ __nv_bfloat16 g_w16 [786432];       // bf16 weights (qkv|proj|fc1|fc2)
#define W16_QKV  0
#define W16_PROJ 196608
#define W16_FC1  262144
#define W16_FC2  524288
__device__ float g_pm  [B_ * 64 * C_];
__device__ float g_ps  [B_ * 64 * C_];
__device__ float g_cmax[B_ * C_];
__device__ float g_cinv[B_ * C_];
__device__ float g_ctxp[16 * B_ * HEADS_ * D_ * D_];
__device__ float g_ctx [B_ * HEADS_ * D_ * D_];
__device__ float g_cps [B_ * 64 * C_];
__device__ float g_cpm [B_ * 64 * C_];
__device__ float g_avg [B_ * C_];
__device__ float g_mx  [B_ * C_];
__device__ float g_ca  [B_ * C_];
__device__ float g_sm  [ROWS_];
__device__ float g_sx  [ROWS_];
__device__ float g_sa  [ROWS_];

__device__ __forceinline__ float geluf(float x) {
    return 0.5f * x * (1.0f + erff(x * 0.70710678118654752440f));
}
__device__ __forceinline__ float sigmf(float x) {
    return 1.0f / (1.0f + __expf(-x));
}
__device__ __forceinline__ void store8(float* p, float4 v) { *(float4*)p = v; }
__device__ __forceinline__ void store8(__nv_bfloat16* p, float4 v) {
    __nv_bfloat162 h0 = __floats2bfloat162_rn(v.x, v.y);
    __nv_bfloat162 h1 = __floats2bfloat162_rn(v.z, v.w);
    uint2 u;
    u.x = *reinterpret_cast<uint32_t*>(&h0);
    u.y = *reinterpret_cast<uint32_t*>(&h1);
    *(uint2*)p = u;
}

// ---------------- fp32 -> bf16 weight conversion (all 4 weights, 1 kernel) --
__global__ void f2bf_all(const float* __restrict__ s0, const float* __restrict__ s1,
                         const float* __restrict__ s2, const float* __restrict__ s3,
                         __nv_bfloat16* __restrict__ dst)
{
    int i = blockIdx.x * blockDim.x + threadIdx.x;
    if (i >= 393216) return;
    int e = i * 2;
    const float* src;
    int off;
    if (e < W16_PROJ)      { src = s0; off = e; }
    else if (e < W16_FC1)  { src = s1; off = e - W16_PROJ; }
    else if (e < W16_FC2)  { src = s2; off = e - W16_FC1; }
    else                   { src = s3; off = e - W16_FC2; }
    float2 v = *(const float2*)(src + off);
    __nv_bfloat162 h = __floats2bfloat162_rn(v.x, v.y);
    *(uint32_t*)(dst + e) = *reinterpret_cast<uint32_t*>(&h);
}

// ---------------- LayerNorm (256 wide), one warp per row --------------------
template <typename OutT>
__global__ void ln256(const float* __restrict__ in, OutT* __restrict__ out,
                      const float* __restrict__ g, const float* __restrict__ bt)
{
    int w = (blockIdx.x * blockDim.x + threadIdx.x) >> 5;
    int lane = threadIdx.x & 31;
    if (w >= ROWS_) return;
    const float* r = in + (size_t)w * C_;
    float4 a = *(const float4*)(r + lane * 4);
    float4 b = *(const float4*)(r + 128 + lane * 4);
    float s = a.x + a.y + a.z + a.w + b.x + b.y + b.z + b.w;
    float q = a.x*a.x + a.y*a.y + a.z*a.z + a.w*a.w
            + b.x*b.x + b.y*b.y + b.z*b.z + b.w*b.w;
    #pragma unroll
    for (int o = 16; o; o >>= 1) {
        s += __shfl_xor_sync(0xffffffffu, s, o);
        q += __shfl_xor_sync(0xffffffffu, q, o);
    }
    float mean = s * (1.0f / C_);
    float inv = rsqrtf(q * (1.0f / C_) - mean * mean + 1e-5f);
    float4 g0 = *(const float4*)(g + lane * 4);
    float4 g1 = *(const float4*)(g + 128 + lane * 4);
    float4 b0 = *(const float4*)(bt + lane * 4);
    float4 b1 = *(const float4*)(bt + 128 + lane * 4);
    float4 o0, o1;
    o0.x = (a.x - mean) * inv * g0.x + b0.x;
    o0.y = (a.y - mean) * inv * g0.y + b0.y;
    o0.z = (a.z - mean) * inv * g0.z + b0.z;
    o0.w = (a.w - mean) * inv * g0.w + b0.w;
    o1.x = (b.x - mean) * inv * g1.x + b1.x;
    o1.y = (b.y - mean) * inv * g1.y + b1.y;
    o1.z = (b.z - mean) * inv * g1.z + b1.z;
    o1.w = (b.w - mean) * inv * g1.w + b1.w;
    OutT* po = out + (size_t)w * C_;
    store8(po + lane * 4, o0);
    store8(po + 128 + lane * 4, o1);
}

// ---- LN1 variant: writes fp32 xn AND a bf16 shadow (for conv taps) ---------
__global__ void ln256_dual(const float* __restrict__ in, float* __restrict__ out,
                           __nv_bfloat16* __restrict__ outb,
                           const float* __restrict__ g, const float* __restrict__ bt)
{
    int w = (blockIdx.x * blockDim.x + threadIdx.x) >> 5;
    int lane = threadIdx.x & 31;
    if (w >= ROWS_) return;
    const float* r = in + (size_t)w * C_;
    float4 a = *(const float4*)(r + lane * 4);
    float4 b = *(const float4*)(r + 128 + lane * 4);
    float s = a.x + a.y + a.z + a.w + b.x + b.y + b.z + b.w;
    float q = a.x*a.x + a.y*a.y + a.z*a.z + a.w*a.w
            + b.x*b.x + b.y*b.y + b.z*b.z + b.w*b.w;
    #pragma unroll
    for (int o = 16; o; o >>= 1) {
        s += __shfl_xor_sync(0xffffffffu, s, o);
        q += __shfl_xor_sync(0xffffffffu, q, o);
    }
    float mean = s * (1.0f / C_);
    float inv = rsqrtf(q * (1.0f / C_) - mean * mean + 1e-5f);
    float4 g0 = *(const float4*)(g + lane * 4);
    float4 g1 = *(const float4*)(g + 128 + lane * 4);
    float4 b0 = *(const float4*)(bt + lane * 4);
    float4 b1 = *(const float4*)(bt + 128 + lane * 4);
    float4 o0, o1;
    o0.x = (a.x - mean) * inv * g0.x + b0.x;
    o0.y = (a.y - mean) * inv * g0.y + b0.y;
    o0.z = (a.z - mean) * inv * g0.z + b0.z;
    o0.w = (a.w - mean) * inv * g0.w + b0.w;
    o1.x = (b.x - mean) * inv * g1.x + b1.x;
    o1.y = (b.y - mean) * inv * g1.y + b1.y;
    o1.z = (b.z - mean) * inv * g1.z + b1.z;
    o1.w = (b.w - mean) * inv * g1.w + b1.w;
    float* po = out + (size_t)w * C_;
    *(float4*)(po + lane * 4) = o0;
    *(float4*)(po + 128 + lane * 4) = o1;
    __nv_bfloat16* pb = outb + (size_t)w * C_;
    store8(pb + lane * 4, o0);
    store8(pb + 128 + lane * 4, o1);
}

// --------- fused: dwconv3(xn_bf16) -> LN -> gelu -> +xn -> bf16 out ---------
__global__ __launch_bounds__(256)
void sr_fuse(const float* __restrict__ xn, const __nv_bfloat16* __restrict__ xnb,
             __nv_bfloat16* __restrict__ out,
             const float* __restrict__ sw, const float* __restrict__ sb,
             const float* __restrict__ ag, const float* __restrict__ ab)
{
    __shared__ float red[16];
    int n = blockIdx.x;
    int b = n >> 12, pos = n & 4095;
    int h = pos >> 6, w = pos & 63;
    int c = threadIdx.x;
    float acc = sb[c];
    #pragma unroll
    for (int dy = -1; dy <= 1; dy++) {
        int hh = h + dy;
        if ((unsigned)hh >= 64u) continue;
        #pragma unroll
        for (int dx = -1; dx <= 1; dx++) {
            int ww = w + dx;
            if ((unsigned)ww >= 64u) continue;
            int k = (dy + 1) * 3 + (dx + 1);
            float v = __bfloat162float(xnb[((size_t)(b * N_ + (hh << 6) + ww)) * C_ + c]);
            acc += v * sw[c * 9 + k];
        }
    }
    float s = acc, q = acc * acc;
    #pragma unroll
    for (int o = 16; o; o >>= 1) {
        s += __shfl_xor_sync(0xffffffffu, s, o);
        q += __shfl_xor_sync(0xffffffffu, q, o);
    }
    int wid = c >> 5, lane = c & 31;
    if (lane == 0) { red[wid] = s; red[8 + wid] = q; }
    __syncthreads();
    if (wid == 0) {
        float ss = (lane < 8) ? red[lane] : 0.0f;
        float qq = (lane < 8) ? red[8 + lane] : 0.0f;
        #pragma unroll
        for (int o = 4; o; o >>= 1) {
            ss += __shfl_xor_sync(0xffffffffu, ss, o);
            qq += __shfl_xor_sync(0xffffffffu, qq, o);
        }
        if (lane == 0) { red[0] = ss; red[1] = qq; }
    }
    __syncthreads();
    float mean = red[0] * (1.0f / C_);
    float inv = rsqrtf(red[1] * (1.0f / C_) - mean * mean + 1e-5f);
    float v = (acc - mean) * inv * ag[c] + ab[c];
    float xa = xn[(size_t)n * C_ + c] + geluf(v);
    out[(size_t)n * C_ + c] = __float2bfloat16_rn(xa);
}

// --------- depthwise 3x3 bf16 + gelu, 4-token sliding window (R6 v2) --------
__global__ __launch_bounds__(256)
void dwconv3_bf16_v2(const __nv_bfloat16* __restrict__ in,
                     __nv_bfloat16* __restrict__ out,
                     const float* __restrict__ w, const float* __restrict__ bias)
{
    const int CH = HID_;
    int tid = threadIdx.x;
    int c0 = (blockIdx.x * 16 + (tid & 15)) * 4;
    int h  = blockIdx.y;
    int b  = blockIdx.z;
    int w0 = (tid >> 4) * 4;

    float wr[4][9];
    #pragma unroll
    for (int i = 0; i < 4; i++)
        #pragma unroll
        for (int k = 0; k < 9; k++)
            wr[i][k] = w[(c0 + i) * 9 + k];

    float acc[4][4];
    #pragma unroll
    for (int t = 0; t < 4; t++)
        #pragma unroll
        for (int i = 0; i < 4; i++)
            acc[t][i] = bias[c0 + i];

    #pragma unroll
    for (int dy = -1; dy <= 1; dy++) {
        int hh = h + dy;
        if ((unsigned)hh >= 64u) continue;
        const __nv_bfloat16* rowp = in + ((size_t)(b * N_ + (hh << 6))) * CH + c0;
        #pragma unroll
        for (int wx = -1; wx <= 4; wx++) {
            int ww = w0 + wx;
            if ((unsigned)ww >= 64u) continue;
            uint2 raw = *(const uint2*)(rowp + (size_t)ww * CH);
            float2 f0 = __bfloat1622float2(*reinterpret_cast<__nv_bfloat162*>(&raw.x));
            float2 f1 = __bfloat1622float2(*reinterpret_cast<__nv_bfloat162*>(&raw.y));
            float f[4] = {f0.x, f0.y, f1.x, f1.y};
            #pragma unroll
            for (int t = 0; t < 4; t++) {
                int kx = wx - t;
                if (kx < -1 || kx > 1) continue;
                int k = (dy + 1) * 3 + kx + 1;
                #pragma unroll
                for (int i = 0; i < 4; i++)
                    acc[t][i] += f[i] * wr[i][k];
            }
        }
    }
    #pragma unroll
    for (int t = 0; t < 4; t++) {
        float4 o = make_float4(geluf(acc[t][0]), geluf(acc[t][1]),
                               geluf(acc[t][2]), geluf(acc[t][3]));
        store8(out + ((size_t)(b * N_ + (h << 6) + w0 + t)) * CH + c0, o);
    }
}

// -------- BF16 GEMM, 3-stage cp.async pipeline, XOR-swizzled smem -----------
#define SSTG 16384                 // bytes per stage per matrix
#define NSTAGE 3

__device__ __forceinline__ void cp16(uint32_t d, const void* s) {
    asm volatile("cp.async.cg.shared.global [%0], [%1], 16;" :: "r"(d), "l"(s));
}

template <typename OutT>
__global__ __launch_bounds__(256, 2)
void gemm_bf16(const __nv_bfloat16* __restrict__ A, const __nv_bfloat16* __restrict__ W,
               OutT* __restrict__ Cout, int M, int N, int K,
               const float* __restrict__ bias,
               const float* __restrict__ r1, const float* __restrict__ r2)
{
    extern __shared__ __nv_bfloat16 sh16[];
    uint32_t sA0 = (uint32_t)__cvta_generic_to_shared(sh16);
    uint32_t sB0 = sA0 + NSTAGE * SSTG;

    int tid = threadIdx.x;
    int warp = tid >> 5, lane = tid & 31;
    int wm = warp >> 2, wn = warp & 3;
    int bm = blockIdx.y * 128, bn = blockIdx.x * 128;
    int gr = lane >> 2, gc = lane & 3;

    float acc[4][4][4];
    #pragma unroll
    for (int i = 0; i < 4; i++)
        #pragma unroll
        for (int j = 0; j < 4; j++)
            #pragma unroll
            for (int q = 0; q < 4; q++) acc[i][j][q] = 0.0f;

    int KT = K >> 6;

    int ldr = tid >> 3;
    int chk = tid & 7;
    uint32_t swd = (uint32_t)(ldr * 128 + ((chk ^ (ldr & 7)) << 4));
    const __nv_bfloat16* Abase = A + (size_t)(bm + ldr) * K + chk * 8;
    const __nv_bfloat16* Wbase = W + (size_t)(bn + ldr) * K + chk * 8;

    #define LOAD_STAGE(st, kb) do {                                            \
        uint32_t so = (st) * SSTG + swd;                                       \
        size_t go = (size_t)(kb) * 64;                                         \
        _Pragma("unroll")                                                      \
        for (int it = 0; it < 4; it++) {                                       \
            cp16(sA0 + so + it * 4096, Abase + (size_t)(it * 32) * K + go);    \
            cp16(sB0 + so + it * 4096, Wbase + (size_t)(it * 32) * K + go);    \
        }                                                                      \
        asm volatile("cp.async.commit_group;");                                \
    } while (0)

    LOAD_STAGE(0, 0);
    if (KT > 1) LOAD_STAGE(1, 1);

    int rA = wm * 64 + (lane & 15);
    int cAx = lane >> 4;
    int sa7 = rA & 7;
    int rB = wn * 32 + (lane & 7);
    int cBx = (lane >> 3) & 1;
    int sb7 = rB & 7;

    int st = 0;
    for (int kb = 0; kb < KT; kb++) {
        asm volatile("cp.async.wait_group 1;");
        __syncthreads();

        uint32_t stA = sA0 + st * SSTG;
        uint32_t stB = sB0 + st * SSTG;
        #pragma unroll
        for (int ks = 0; ks < 4; ks++) {
            uint32_t a[4][4], b[4][2];
            uint32_t ca = (uint32_t)(((ks * 2 + cAx) ^ sa7) << 4);
            uint32_t cb = (uint32_t)(((ks * 2 + cBx) ^ sb7) << 4);
            #pragma unroll
            for (int i = 0; i < 4; i++) {
                uint32_t addr = stA + (uint32_t)((rA + i * 16) * 128) + ca;
                asm volatile(
                    "ldmatrix.sync.aligned.m8n8.x4.shared.b16 {%0,%1,%2,%3}, [%4];"
                    : "=r"(a[i][0]), "=r"(a[i][1]), "=r"(a[i][2]), "=r"(a[i][3])
                    : "r"(addr));
            }
            #pragma unroll
            for (int j = 0; j < 4; j++) {
                uint32_t addr = stB + (uint32_t)((rB + j * 8) * 128) + cb;
                asm volatile(
                    "ldmatrix.sync.aligned.m8n8.x2.shared.b16 {%0,%1}, [%2];"
                    : "=r"(b[j][0]), "=r"(b[j][1])
                    : "r"(addr));
            }
            #pragma unroll
            for (int i = 0; i < 4; i++)
                #pragma unroll
                for (int j = 0; j < 4; j++)
                    asm volatile(
                        "mma.sync.aligned.m16n8k16.row.col.f32.bf16.bf16.f32 "
                        "{%0,%1,%2,%3}, {%4,%5,%6,%7}, {%8,%9}, {%0,%1,%2,%3};"
                        : "+f"(acc[i][j][0]), "+f"(acc[i][j][1]),
                          "+f"(acc[i][j][2]), "+f"(acc[i][j][3])
                        : "r"(a[i][0]), "r"(a[i][1]), "r"(a[i][2]), "r"(a[i][3]),
                          "r"(b[j][0]), "r"(b[j][1]));
        }
        if (kb + 2 < KT) {
            int nst = st + 2; if (nst >= NSTAGE) nst -= NSTAGE;
            LOAD_STAGE(nst, kb + 2);
        }
        st++; if (st == NSTAGE) st = 0;
    }

    #pragma unroll
    for (int i = 0; i < 4; i++) {
        int row0 = bm + wm * 64 + i * 16 + gr;
        #pragma unroll
        for (int j = 0; j < 4; j++) {
            int col = bn + wn * 32 + j * 8 + gc * 2;
            float bx = 0.f, by = 0.f;
            if (bias) { bx = bias[col]; by = bias[col + 1]; }
            size_t o0 = (size_t)row0 * N + col;
            size_t o1 = (size_t)(row0 + 8) * N + col;
            float v0 = acc[i][j][0] + bx, v1 = acc[i][j][1] + by;
            float v2 = acc[i][j][2] + bx, v3 = acc[i][j][3] + by;
            if (r1) {
                float2 p0 = *(const float2*)(r1 + o0);
                float2 p1 = *(const float2*)(r1 + o1);
                v0 += p0.x; v1 += p0.y; v2 += p1.x; v3 += p1.y;
            }
            if (r2) {
                float2 p0 = *(const float2*)(r2 + o0);
                float2 p1 = *(const float2*)(r2 + o1);
                v0 += p0.x; v1 += p0.y; v2 += p1.x; v3 += p1.y;
            }
            if constexpr (sizeof(OutT) == 4) {
                *(float2*)((float*)Cout + o0) = make_float2(v0, v1);
                *(float2*)((float*)Cout + o1) = make_float2(v2, v3);
            } else {
                __nv_bfloat162 h0 = __floats2bfloat162_rn(v0, v1);
                __nv_bfloat162 h1 = __floats2bfloat162_rn(v2, v3);
                *(uint32_t*)((__nv_bfloat16*)Cout + o0) = *reinterpret_cast<uint32_t*>(&h0);
                *(uint32_t*)((__nv_bfloat16*)Cout + o1) = *reinterpret_cast<uint32_t*>(&h1);
            }
        }
    }
}

// ---------------- q softmax over tokens: per-(b,c) online partials ----------
__global__ void qsoft_part(const __nv_bfloat16* __restrict__ qkv)
{
    int b = blockIdx.x, ch = blockIdx.y, c = threadIdx.x;
    const __nv_bfloat16* p = qkv + ((size_t)(b * N_ + ch * 64)) * (3 * C_) + c;
    float m = -1e30f, s = 0.0f;
    for (int i = 0; i < 64; i++) {
        float v = __bfloat162float(p[(size_t)i * (3 * C_)]);
        float nm = fmaxf(m, v);
        s = s * __expf(m - nm) + __expf(v - nm);
        m = nm;
    }
    g_pm[(b * 64 + ch) * C_ + c] = m;
    g_ps[(b * 64 + ch) * C_ + c] = s;
}

__global__ void qsoft_comb()
{
    int idx = blockIdx.x * blockDim.x + threadIdx.x;
    if (idx >= B_ * C_) return;
    int b = idx >> 8, c = idx & 255;
    float M = -1e30f;
    for (int ch = 0; ch < 64; ch++) M = fmaxf(M, g_pm[(b * 64 + ch) * C_ + c]);
    float S = 0.0f;
    for (int ch = 0; ch < 64; ch++)
        S += g_ps[(b * 64 + ch) * C_ + c] * __expf(g_pm[(b * 64 + ch) * C_ + c] - M);
    g_cmax[idx] = M;
    g_cinv[idx] = 1.0f / S;
}

// ---------------- ctx = softmax_d(k)^T @ v ----------------------------------
__global__ __launch_bounds__(256) void ctx_kernel(const __nv_bfloat16* __restrict__ qkv)
{
    int chunk = blockIdx.x;
    int head  = blockIdx.y;
    int b     = blockIdx.z;
    __shared__ float ks[32][33];
    __shared__ float vs[32][33];
    int tid = threadIdx.x, lane = tid & 31, wp = tid >> 5;
    float acc[4] = {0.f, 0.f, 0.f, 0.f};
    for (int it = 0; it < 8; it++) {
        int nb = chunk * 256 + it * 32;
        #pragma unroll
        for (int j = 0; j < 8; j++) {
            int id = tid + 256 * j;
            int r = id >> 6, inner = id & 63;
            const __nv_bfloat16* src =
                qkv + ((size_t)(b * N_ + nb + r)) * (3 * C_) + C_ + head * D_;
            if (inner < 32) ks[r][inner] = __bfloat162float(src[inner]);
            else            vs[r][inner - 32] = __bfloat162float(src[C_ + inner - 32]);
        }
        __syncthreads();
        #pragma unroll
        for (int rr = 0; rr < 4; rr++) {
            int r = wp * 4 + rr;
            float v = ks[r][lane];
            float mx = v;
            #pragma unroll
            for (int o = 16; o; o >>= 1) mx = fmaxf(mx, __shfl_xor_sync(0xffffffffu, mx, o));
            float e = __expf(v - mx);
            float su = e;
            #pragma unroll
            for (int o = 16; o; o >>= 1) su += __shfl_xor_sync(0xffffffffu, su, o);
            ks[r][lane] = e / su;
        }
        __syncthreads();
        #pragma unroll
        for (int r = 0; r < 32; r++) {
            float vv = vs[r][lane];
            #pragma unroll
            for (int i = 0; i < 4; i++) acc[i] += ks[r][wp + 8 * i] * vv;
        }
        __syncthreads();
    }
    #pragma unroll
    for (int i = 0; i < 4; i++) {
        int e = wp + 8 * i;
        g_ctxp[(size_t)chunk * (B_ * HEADS_ * D_ * D_) +
               ((b * HEADS_ + head) * D_ + e) * D_ + lane] = acc[i];
    }
}

__global__ void ctx_comb()
{
    int idx = blockIdx.x * blockDim.x + threadIdx.x;
    if (idx >= B_ * HEADS_ * D_ * D_) return;
    float s = 0.0f;
    for (int ch = 0; ch < 16; ch++) s += g_ctxp[(size_t)ch * (B_ * HEADS_ * D_ * D_) + idx];
    g_ctx[idx] = s;
}

// ---------------- attn = softmax_N(q) @ ctx ---------------------------------
__global__ __launch_bounds__(256) void attn2(const __nv_bfloat16* __restrict__ qkv,
                                             __nv_bfloat16* __restrict__ out)
{
    int b = blockIdx.y;
    int base = blockIdx.x * 64;
    int h = threadIdx.x >> 5;
    int lane = threadIdx.x & 31;
    int ch = h * 32 + lane;

    float cm = g_cmax[b * C_ + ch];
    float ci = g_cinv[b * C_ + ch];
    float ctxr[32];
    #pragma unroll
    for (int e = 0; e < 32; e++)
        ctxr[e] = g_ctx[((b * HEADS_ + h) * D_ + e) * D_ + lane];

    const __nv_bfloat16* qbase = qkv + (size_t)(b * N_ + base) * (3 * C_) + ch;
    __nv_bfloat16* obase = out + (size_t)(b * N_ + base) * C_ + ch;
    for (int t = 0; t < 64; t++) {
        float q = __bfloat162float(qbase[(size_t)t * (3 * C_)]);
        float p = __expf(q - cm) * ci;
        float acc = 0.0f;
        #pragma unroll
        for (int e = 0; e < 32; e++)
            acc += __shfl_sync(0xffffffffu, p, e) * ctxr[e];
        obase[(size_t)t * C_] = __float2bfloat16_rn(acc);
    }
}

// ---------------- CSDA ------------------------------------------------------
__global__ void cpool_part(const float* __restrict__ x3)
{
    int b = blockIdx.x, ch = blockIdx.y, c = threadIdx.x;
    const float* p = x3 + ((size_t)(b * N_ + ch * 64)) * C_ + c;
    float s = 0.0f, m = -1e30f;
    for (int i = 0; i < 64; i++) {
        float v = p[(size_t)i * C_];
        s += v; m = fmaxf(m, v);
    }
    g_cps[(b * 64 + ch) * C_ + c] = s;
    g_cpm[(b * 64 + ch) * C_ + c] = m;
}

__global__ void cpool_comb()
{
    int idx = blockIdx.x * blockDim.x + threadIdx.x;
    if (idx >= B_ * C_) return;
    int b = idx >> 8, c = idx & 255;
    float s = 0.0f, m = -1e30f;
    for (int ch = 0; ch < 64; ch++) {
        s += g_cps[(b * 64 + ch) * C_ + c];
        m = fmaxf(m, g_cpm[(b * 64 + ch) * C_ + c]);
    }
    g_avg[idx] = s * (1.0f / N_);
    g_mx[idx] = m;
}

__global__ void ca_mlp(const float* __restrict__ w1, const float* __restrict__ w2)
{
    int b = blockIdx.x, t = threadIdx.x;
    __shared__ float hsum[16];
    if (t < 16) {
        float sa = 0.0f, sm = 0.0f;
        for (int c = 0; c < C_; c++) {
            float w = w1[t * C_ + c];
            sa += g_avg[b * C_ + c] * w;
            sm += g_mx[b * C_ + c] * w;
        }
        hsum[t] = fmaxf(sa, 0.0f) + fmaxf(sm, 0.0f);
    }
    __syncthreads();
    float acc = 0.0f;
    #pragma unroll
    for (int j = 0; j < 16; j++) acc += w2[t * 16 + j] * hsum[j];
    g_ca[b * C_ + t] = sigmf(acc);
}

__global__ void spool(const float* __restrict__ x3)
{
    int w = (blockIdx.x * blockDim.x + threadIdx.x) >> 5;
    int lane = threadIdx.x & 31;
    if (w >= ROWS_) return;
    int b = w >> 12;
    const float* r = x3 + (size_t)w * C_;
    const float* ca = g_ca + b * C_;
    float4 a = *(const float4*)(r + lane * 4);
    float4 c0 = *(const float4*)(ca + lane * 4);
    float4 bvals = *(const float4*)(r + 128 + lane * 4);
    float4 c1 = *(const float4*)(ca + 128 + lane * 4);
    float v0 = a.x * c0.x, v1 = a.y * c0.y, v2 = a.z * c0.z, v3 = a.w * c0.w;
    float v4 = bvals.x * c1.x, v5 = bvals.y * c1.y, v6 = bvals.z * c1.z, v7 = bvals.w * c1.w;
    float s = v0 + v1 + v2 + v3 + v4 + v5 + v6 + v7;
    float m = fmaxf(fmaxf(fmaxf(v0, v1), fmaxf(v2, v3)), fmaxf(fmaxf(v4, v5), fmaxf(v6, v7)));
    #pragma unroll
    for (int o = 16; o; o >>= 1) {
        s += __shfl_xor_sync(0xffffffffu, s, o);
        m = fmaxf(m, __shfl_xor_sync(0xffffffffu, m, o));
    }
    if (lane == 0) {
        g_sm[w] = s * (1.0f / C_);
        g_sx[w] = m;
    }
}

__global__ void conv7(const float* __restrict__ spw, const float* __restrict__ spb)
{
    int idx = blockIdx.x * blockDim.x + threadIdx.x;
    if (idx >= ROWS_) return;
    int b = idx >> 12, n = idx & 4095;
    int h = n >> 6, w = n & 63;
    float acc = spb[0];
    #pragma unroll
    for (int ch = 0; ch < 2; ch++) {
        const float* src = ch ? g_sx : g_sm;
        const float* wp = spw + ch * 49;
        for (int ky = 0; ky < 7; ky++) {
            int y = h + ky - 3;
            if ((unsigned)y >= 64u) continue;
            for (int kx = 0; kx < 7; kx++) {
                int x = w + kx - 3;
                if ((unsigned)x >= 64u) continue;
                acc += src[(b << 12) + (y << 6) + x] * wp[ky * 7 + kx];
            }
        }
    }
    g_sa[idx] = sigmf(acc);
}

__global__ void final_scale(const float* __restrict__ x3, float* __restrict__ out)
{
    int idx = blockIdx.x * blockDim.x + threadIdx.x;
    if (idx >= ROWS_ * 64) return;
    int c4 = idx & 63;
    int row = idx >> 6;
    int b = row >> 12;
    float4 v = *(const float4*)(x3 + (size_t)row * C_ + c4 * 4);
    float4 ca = *(const float4*)(g_ca + b * C_ + c4 * 4);
    float sa = g_sa[row];
    v.x *= ca.x * sa; v.y *= ca.y * sa; v.z *= ca.z * sa; v.w *= ca.w * sa;
    *(float4*)(out + (size_t)row * C_ + c4 * 4) = v;
}

// ---------------------------------------------------------------------------
extern "C" void kernel_launch(void* const* d_in, const int* in_sizes, int n_in,
                              void* d_out, int out_size)
{
    int p = (n_in >= 24 && in_sizes[1] == 1 && in_sizes[2] == 1) ? 3 : 1;
    const float* x      = (const float*)d_in[0];
    const float* n1_g   = (const float*)d_in[p + 0];
    const float* n1_b   = (const float*)d_in[p + 1];
    const float* sr_w   = (const float*)d_in[p + 2];
    const float* sr_b   = (const float*)d_in[p + 3];
    const float* an_g   = (const float*)d_in[p + 4];
    const float* an_b   = (const float*)d_in[p + 5];
    const float* qkv_w  = (const float*)d_in[p + 6];
    const float* proj_w = (const float*)d_in[p + 7];
    const float* proj_b = (const float*)d_in[p + 8];
    const float* n2_g   = (const float*)d_in[p + 9];
    const float* n2_b   = (const float*)d_in[p + 10];
    const float* fc1_w  = (const float*)d_in[p + 11];
    const float* fc1_b  = (const float*)d_in[p + 12];
    const float* dw_w   = (const float*)d_in[p + 13];
    const float* dw_b   = (const float*)d_in[p + 14];
    const float* fc2_w  = (const float*)d_in[p + 15];
    const float* fc2_b  = (const float*)d_in[p + 16];
    const float* ca_w1  = (const float*)d_in[p + 17];
    const float* ca_w2  = (const float*)d_in[p + 18];
    const float* sp_w   = (const float*)d_in[p + 19];
    const float* sp_b   = (const float*)d_in[p + 20];
    float* out = (float*)d_out;

    float *pxn, *pb1, *pb2;
    __nv_bfloat16 *pqkv16, *pa16, *ph16a, *ph16b, *pw16;
    cudaGetSymbolAddress((void**)&pxn,    g_xn);
    cudaGetSymbolAddress((void**)&pb1,    g_b1);
    cudaGetSymbolAddress((void**)&pb2,    g_b2);
    cudaGetSymbolAddress((void**)&pqkv16, g_qkv16);
    cudaGetSymbolAddress((void**)&pa16,   g_a16);
    cudaGetSymbolAddress((void**)&ph16a,  g_h16a);
    cudaGetSymbolAddress((void**)&ph16b,  g_h16b);
    cudaGetSymbolAddress((void**)&pw16,   g_w16);

    const int TPB = 256;
    const int GEMM_SMEM = NSTAGE * SSTG * 2;   // 98304 bytes
    cudaFuncSetAttribute(gemm_bf16<float>, cudaFuncAttributeMaxDynamicSharedMemorySize,
                         GEMM_SMEM);
    cudaFuncSetAttribute(gemm_bf16<__nv_bfloat16>, cudaFuncAttributeMaxDynamicSharedMemorySize,
                         GEMM_SMEM);

    // 0. bf16 weight conversion (one kernel)
    f2bf_all<<<(393216 + TPB - 1) / TPB, TPB>>>(qkv_w, proj_w, fc1_w, fc2_w, pw16);

    // 1. xn = LN1(x)  (fp32 + bf16 shadow into h16b, reused later by dwconv)
    ln256_dual<<<ROWS_ * 32 / TPB, TPB>>>(x, pxn, ph16b, n1_g, n1_b);
    // 2+3. xa16 = bf16(xn + gelu(LN_act(dwconv3(xn_bf16))))  (fused)
    sr_fuse<<<ROWS_, TPB>>>(pxn, ph16b, pa16, sr_w, sr_b, an_g, an_b);
    // 4. qkv = xa @ qkv_w^T  (bf16 out)
    {
        dim3 g(3 * C_ / 128, ROWS_ / 128);
        gemm_bf16<__nv_bfloat16><<<g, TPB, GEMM_SMEM>>>(pa16, pw16 + W16_QKV, pqkv16,
                                                        ROWS_, 3 * C_, C_, nullptr, nullptr, nullptr);
    }
    // 5. q column-softmax stats
    {
        dim3 g(B_, 64);
        qsoft_part<<<g, TPB>>>(pqkv16);
        qsoft_comb<<<(B_ * C_ + TPB - 1) / TPB, TPB>>>();
    }
    // 6. ctx = softmax_d(k)^T v
    {
        dim3 g(16, HEADS_, B_);
        ctx_kernel<<<g, TPB>>>(pqkv16);
        ctx_comb<<<(B_ * HEADS_ * D_ * D_ + TPB - 1) / TPB, TPB>>>();
    }
    // 7. attn = softmax_N(q) @ ctx -> a16 (bf16)
    {
        dim3 g(N_ / 64, B_);
        attn2<<<g, TPB>>>(pqkv16, pa16);
    }
    // 8. x2 = x + attn @ proj_w^T + proj_b + xn -> b1
    {
        dim3 g(C_ / 128, ROWS_ / 128);
        gemm_bf16<float><<<g, TPB, GEMM_SMEM>>>(pa16, pw16 + W16_PROJ, pb1,
                                                ROWS_, C_, C_, proj_b, x, pxn);
    }
    // 9. ln2(x2) -> a16 (bf16)
    ln256<__nv_bfloat16><<<ROWS_ * 32 / TPB, TPB>>>(pb1, pa16, n2_g, n2_b);
    // 10. fc1 -> h16a (bf16)
    {
        dim3 g(HID_ / 128, ROWS_ / 128);
        gemm_bf16<__nv_bfloat16><<<g, TPB, GEMM_SMEM>>>(pa16, pw16 + W16_FC1, ph16a,
                                                        ROWS_, HID_, C_, fc1_b, nullptr, nullptr);
    }
    // 11. dwconv + gelu (bf16, sliding window) -> h16b (shadow no longer needed)
    {
        dim3 g(HID_ / 4 / 16, 64, B_);
        dwconv3_bf16_v2<<<g, TPB>>>(ph16a, ph16b, dw_w, dw_b);
    }
    // 12. x3 = x2 + gelu_dw @ fc2_w^T + fc2_b -> b2
    {
        dim3 g(C_ / 128, ROWS_ / 128);
        gemm_bf16<float><<<g, TPB, GEMM_SMEM>>>(ph16b, pw16 + W16_FC2, pb2,
                                                ROWS_, C_, HID_, fc2_b, pb1, nullptr);
    }
    // 13. channel pools
    {
        dim3 g(B_, 64);
        cpool_part<<<g, TPB>>>(pb2);
        cpool_comb<<<(B_ * C_ + TPB - 1) / TPB, TPB>>>();
    }
    // 14. channel attention MLP
    ca_mlp<<<B_, TPB>>>(ca_w1, ca_w2);
    // 15. spatial pools of x3*ca
    spool<<<ROWS_ * 32 / TPB, TPB>>>(pb2);
    // 16. 7x7 spatial conv -> sa
    conv7<<<(ROWS_ + TPB - 1) / TPB, TPB>>>(sp_w, sp_b);
    // 17. out = x3 * ca * sa
    final_scale<<<(ROWS_ * 64 + TPB - 1) / TPB, TPB>>>(pb2, out);
}

// round 14
// speedup vs baseline: 1.0306x; 1.0306x over previous
#include <cuda_runtime.h>
#include <cuda_bf16.h>
#include <math.h>
#include <stdint.h>

// Problem constants
#define B_    16
#define N_    4096
#define C_    256
#define HEADS_ 8
#define D_    32
#define HID_  1024
#define ROWS_ 65536          // B_*N_

// ---------------- scratch (device globals; no allocation allowed) ----------
__device__ float g_xn  [ROWS_ * C_];           // norm1(x)
__device__ float g_b1  [ROWS_ * C_];           // x2
__device__ float g_b2  [ROWS_ * C_];           // x3
__device__ __nv_bfloat16 g_qkv16[ROWS_ * 3 * C_]; // qkv (bf16)
__device__ __nv_bfloat16 g_a16 [ROWS_ * C_];   // xa / attn / ln2 (bf16, reused)
__device__ __nv_bfloat16 g_h16a[ROWS_ * HID_]; // fc1 out (bf16)
__device__ __nv_bfloat16 g_h16b[ROWS_ * HID_]; // dwconv+gelu out (bf16)
__device__ __nv_bfloat16 g_w16 [786432];       // bf16 weights (qkv|proj|fc1|fc2)
#define W16_QKV  0
#define W16_PROJ 196608
#define W16_FC1  262144
#define W16_FC2  524288
__device__ float g_pm  [B_ * 64 * C_];
__device__ float g_ps  [B_ * 64 * C_];
__device__ float g_cmax[B_ * C_];
__device__ float g_cinv[B_ * C_];
__device__ float g_ctxp[16 * B_ * HEADS_ * D_ * D_];
__device__ float g_ctx [B_ * HEADS_ * D_ * D_];
__device__ float g_cps [B_ * 64 * C_];
__device__ float g_cpm [B_ * 64 * C_];
__device__ float g_avg [B_ * C_];
__device__ float g_mx  [B_ * C_];
__device__ float g_ca  [B_ * C_];
__device__ float g_sm  [ROWS_];
__device__ float g_sx  [ROWS_];
__device__ float g_sa  [ROWS_];

__device__ __forceinline__ float geluf(float x) {
    return 0.5f * x * (1.0f + erff(x * 0.70710678118654752440f));
}
__device__ __forceinline__ float sigmf(float x) {
    return 1.0f / (1.0f + __expf(-x));
}
__device__ __forceinline__ void store8(float* p, float4 v) { *(float4*)p = v; }
__device__ __forceinline__ void store8(__nv_bfloat16* p, float4 v) {
    __nv_bfloat162 h0 = __floats2bfloat162_rn(v.x, v.y);
    __nv_bfloat162 h1 = __floats2bfloat162_rn(v.z, v.w);
    uint2 u;
    u.x = *reinterpret_cast<uint32_t*>(&h0);
    u.y = *reinterpret_cast<uint32_t*>(&h1);
    *(uint2*)p = u;
}

// ---------------- fp32 -> bf16 weight conversion (all 4 weights, 1 kernel) --
__global__ void f2bf_all(const float* __restrict__ s0, const float* __restrict__ s1,
                         const float* __restrict__ s2, const float* __restrict__ s3,
                         __nv_bfloat16* __restrict__ dst)
{
    int i = blockIdx.x * blockDim.x + threadIdx.x;
    if (i >= 393216) return;
    int e = i * 2;
    const float* src;
    int off;
    if (e < W16_PROJ)      { src = s0; off = e; }
    else if (e < W16_FC1)  { src = s1; off = e - W16_PROJ; }
    else if (e < W16_FC2)  { src = s2; off = e - W16_FC1; }
    else                   { src = s3; off = e - W16_FC2; }
    float2 v = *(const float2*)(src + off);
    __nv_bfloat162 h = __floats2bfloat162_rn(v.x, v.y);
    *(uint32_t*)(dst + e) = *reinterpret_cast<uint32_t*>(&h);
}

// ---------------- LayerNorm (256 wide), one warp per row --------------------
template <typename OutT>
__global__ void ln256(const float* __restrict__ in, OutT* __restrict__ out,
                      const float* __restrict__ g, const float* __restrict__ bt)
{
    int w = (blockIdx.x * blockDim.x + threadIdx.x) >> 5;
    int lane = threadIdx.x & 31;
    if (w >= ROWS_) return;
    const float* r = in + (size_t)w * C_;
    float4 a = *(const float4*)(r + lane * 4);
    float4 b = *(const float4*)(r + 128 + lane * 4);
    float s = a.x + a.y + a.z + a.w + b.x + b.y + b.z + b.w;
    float q = a.x*a.x + a.y*a.y + a.z*a.z + a.w*a.w
            + b.x*b.x + b.y*b.y + b.z*b.z + b.w*b.w;
    #pragma unroll
    for (int o = 16; o; o >>= 1) {
        s += __shfl_xor_sync(0xffffffffu, s, o);
        q += __shfl_xor_sync(0xffffffffu, q, o);
    }
    float mean = s * (1.0f / C_);
    float inv = rsqrtf(q * (1.0f / C_) - mean * mean + 1e-5f);
    float4 g0 = *(const float4*)(g + lane * 4);
    float4 g1 = *(const float4*)(g + 128 + lane * 4);
    float4 b0 = *(const float4*)(bt + lane * 4);
    float4 b1 = *(const float4*)(bt + 128 + lane * 4);
    float4 o0, o1;
    o0.x = (a.x - mean) * inv * g0.x + b0.x;
    o0.y = (a.y - mean) * inv * g0.y + b0.y;
    o0.z = (a.z - mean) * inv * g0.z + b0.z;
    o0.w = (a.w - mean) * inv * g0.w + b0.w;
    o1.x = (b.x - mean) * inv * g1.x + b1.x;
    o1.y = (b.y - mean) * inv * g1.y + b1.y;
    o1.z = (b.z - mean) * inv * g1.z + b1.z;
    o1.w = (b.w - mean) * inv * g1.w + b1.w;
    OutT* po = out + (size_t)w * C_;
    store8(po + lane * 4, o0);
    store8(po + 128 + lane * 4, o1);
}

// --------- fused: dwconv3(xn) -> LN -> gelu -> +xn -> bf16 out --------------
__global__ __launch_bounds__(256)
void sr_fuse(const float* __restrict__ xn, __nv_bfloat16* __restrict__ out,
             const float* __restrict__ sw, const float* __restrict__ sb,
             const float* __restrict__ ag, const float* __restrict__ ab)
{
    __shared__ float red[16];
    int n = blockIdx.x;
    int b = n >> 12, pos = n & 4095;
    int h = pos >> 6, w = pos & 63;
    int c = threadIdx.x;
    float acc = sb[c];
    #pragma unroll
    for (int dy = -1; dy <= 1; dy++) {
        int hh = h + dy;
        if ((unsigned)hh >= 64u) continue;
        #pragma unroll
        for (int dx = -1; dx <= 1; dx++) {
            int ww = w + dx;
            if ((unsigned)ww >= 64u) continue;
            int k = (dy + 1) * 3 + (dx + 1);
            acc += xn[((size_t)(b * N_ + (hh << 6) + ww)) * C_ + c] * sw[c * 9 + k];
        }
    }
    float s = acc, q = acc * acc;
    #pragma unroll
    for (int o = 16; o; o >>= 1) {
        s += __shfl_xor_sync(0xffffffffu, s, o);
        q += __shfl_xor_sync(0xffffffffu, q, o);
    }
    int wid = c >> 5, lane = c & 31;
    if (lane == 0) { red[wid] = s; red[8 + wid] = q; }
    __syncthreads();
    if (wid == 0) {
        float ss = (lane < 8) ? red[lane] : 0.0f;
        float qq = (lane < 8) ? red[8 + lane] : 0.0f;
        #pragma unroll
        for (int o = 4; o; o >>= 1) {
            ss += __shfl_xor_sync(0xffffffffu, ss, o);
            qq += __shfl_xor_sync(0xffffffffu, qq, o);
        }
        if (lane == 0) { red[0] = ss; red[1] = qq; }
    }
    __syncthreads();
    float mean = red[0] * (1.0f / C_);
    float inv = rsqrtf(red[1] * (1.0f / C_) - mean * mean + 1e-5f);
    float v = (acc - mean) * inv * ag[c] + ab[c];
    float xa = xn[(size_t)n * C_ + c] + geluf(v);
    out[(size_t)n * C_ + c] = __float2bfloat16_rn(xa);
}

// --------- depthwise 3x3 bf16 + gelu, 4-token sliding window ----------------
__global__ __launch_bounds__(256)
void dwconv3_bf16_v2(const __nv_bfloat16* __restrict__ in,
                     __nv_bfloat16* __restrict__ out,
                     const float* __restrict__ w, const float* __restrict__ bias)
{
    const int CH = HID_;
    int tid = threadIdx.x;
    int c0 = (blockIdx.x * 16 + (tid & 15)) * 4;
    int h  = blockIdx.y;
    int b  = blockIdx.z;
    int w0 = (tid >> 4) * 4;

    float wr[4][9];
    #pragma unroll
    for (int i = 0; i < 4; i++)
        #pragma unroll
        for (int k = 0; k < 9; k++)
            wr[i][k] = w[(c0 + i) * 9 + k];

    float acc[4][4];
    #pragma unroll
    for (int t = 0; t < 4; t++)
        #pragma unroll
        for (int i = 0; i < 4; i++)
            acc[t][i] = bias[c0 + i];

    #pragma unroll
    for (int dy = -1; dy <= 1; dy++) {
        int hh = h + dy;
        if ((unsigned)hh >= 64u) continue;
        const __nv_bfloat16* rowp = in + ((size_t)(b * N_ + (hh << 6))) * CH + c0;
        #pragma unroll
        for (int wx = -1; wx <= 4; wx++) {
            int ww = w0 + wx;
            if ((unsigned)ww >= 64u) continue;
            uint2 raw = *(const uint2*)(rowp + (size_t)ww * CH);
            float2 f0 = __bfloat1622float2(*reinterpret_cast<__nv_bfloat162*>(&raw.x));
            float2 f1 = __bfloat1622float2(*reinterpret_cast<__nv_bfloat162*>(&raw.y));
            float f[4] = {f0.x, f0.y, f1.x, f1.y};
            #pragma unroll
            for (int t = 0; t < 4; t++) {
                int kx = wx - t;
                if (kx < -1 || kx > 1) continue;
                int k = (dy + 1) * 3 + kx + 1;
                #pragma unroll
                for (int i = 0; i < 4; i++)
                    acc[t][i] += f[i] * wr[i][k];
            }
        }
    }
    #pragma unroll
    for (int t = 0; t < 4; t++) {
        float4 o = make_float4(geluf(acc[t][0]), geluf(acc[t][1]),
                               geluf(acc[t][2]), geluf(acc[t][3]));
        store8(out + ((size_t)(b * N_ + (h << 6) + w0 + t)) * CH + c0, o);
    }
}

// -------- BF16 GEMM, 3-stage cp.async pipeline, XOR-swizzled smem -----------
// tile 128x128x64; 8 warps (2m x 4n); warp 64x32 via m16n8k16 + ldmatrix.
#define SSTG 16384                 // bytes per stage per matrix
#define NSTAGE 3

__device__ __forceinline__ void cp16(uint32_t d, const void* s) {
    asm volatile("cp.async.cg.shared.global [%0], [%1], 16;" :: "r"(d), "l"(s));
}

template <typename OutT>
__global__ __launch_bounds__(256, 2)
void gemm_bf16(const __nv_bfloat16* __restrict__ A, const __nv_bfloat16* __restrict__ W,
               OutT* __restrict__ Cout, int M, int N, int K,
               const float* __restrict__ bias,
               const float* __restrict__ r1, const float* __restrict__ r2)
{
    extern __shared__ __nv_bfloat16 sh16[];
    uint32_t sA0 = (uint32_t)__cvta_generic_to_shared(sh16);
    uint32_t sB0 = sA0 + NSTAGE * SSTG;

    int tid = threadIdx.x;
    int warp = tid >> 5, lane = tid & 31;
    int wm = warp >> 2, wn = warp & 3;
    int bm = blockIdx.y * 128, bn = blockIdx.x * 128;
    int gr = lane >> 2, gc = lane & 3;

    float acc[4][4][4];
    #pragma unroll
    for (int i = 0; i < 4; i++)
        #pragma unroll
        for (int j = 0; j < 4; j++)
            #pragma unroll
            for (int q = 0; q < 4; q++) acc[i][j][q] = 0.0f;

    int KT = K >> 6;

    int ldr = tid >> 3;
    int chk = tid & 7;
    uint32_t swd = (uint32_t)(ldr * 128 + ((chk ^ (ldr & 7)) << 4));
    const __nv_bfloat16* Abase = A + (size_t)(bm + ldr) * K + chk * 8;
    const __nv_bfloat16* Wbase = W + (size_t)(bn + ldr) * K + chk * 8;

    #define LOAD_STAGE(st, kb) do {                                            \
        uint32_t so = (st) * SSTG + swd;                                       \
        size_t go = (size_t)(kb) * 64;                                         \
        _Pragma("unroll")                                                      \
        for (int it = 0; it < 4; it++) {                                       \
            cp16(sA0 + so + it * 4096, Abase + (size_t)(it * 32) * K + go);    \
            cp16(sB0 + so + it * 4096, Wbase + (size_t)(it * 32) * K + go);    \
        }                                                                      \
        asm volatile("cp.async.commit_group;");                                \
    } while (0)

    LOAD_STAGE(0, 0);
    if (KT > 1) LOAD_STAGE(1, 1);

    int rA = wm * 64 + (lane & 15);
    int cAx = lane >> 4;
    int sa7 = rA & 7;
    int rB = wn * 32 + (lane & 7);
    int cBx = (lane >> 3) & 1;
    int sb7 = rB & 7;

    // hoist per-ks swizzled column offsets + row bases out of the k-loop
    uint32_t caO[4], cbO[4];
    #pragma unroll
    for (int ks = 0; ks < 4; ks++) {
        caO[ks] = (uint32_t)(((ks * 2 + cAx) ^ sa7) << 4);
        cbO[ks] = (uint32_t)(((ks * 2 + cBx) ^ sb7) << 4);
    }
    uint32_t rAb[4], rBb[4];
    #pragma unroll
    for (int i = 0; i < 4; i++) rAb[i] = (uint32_t)((rA + i * 16) * 128);
    #pragma unroll
    for (int j = 0; j < 4; j++) rBb[j] = (uint32_t)((rB + j * 8) * 128);

    int st = 0;
    for (int kb = 0; kb < KT; kb++) {
        asm volatile("cp.async.wait_group 1;");
        __syncthreads();

        uint32_t stA = sA0 + st * SSTG;
        uint32_t stB = sB0 + st * SSTG;
        #pragma unroll
        for (int ks = 0; ks < 4; ks++) {
            uint32_t a[4][4], b[4][2];
            #pragma unroll
            for (int i = 0; i < 4; i++) {
                uint32_t addr = stA + rAb[i] + caO[ks];
                asm volatile(
                    "ldmatrix.sync.aligned.m8n8.x4.shared.b16 {%0,%1,%2,%3}, [%4];"
                    : "=r"(a[i][0]), "=r"(a[i][1]), "=r"(a[i][2]), "=r"(a[i][3])
                    : "r"(addr));
            }
            #pragma unroll
            for (int j = 0; j < 4; j++) {
                uint32_t addr = stB + rBb[j] + cbO[ks];
                asm volatile(
                    "ldmatrix.sync.aligned.m8n8.x2.shared.b16 {%0,%1}, [%2];"
                    : "=r"(b[j][0]), "=r"(b[j][1])
                    : "r"(addr));
            }
            #pragma unroll
            for (int i = 0; i < 4; i++)
                #pragma unroll
                for (int j = 0; j < 4; j++)
                    asm volatile(
                        "mma.sync.aligned.m16n8k16.row.col.f32.bf16.bf16.f32 "
                        "{%0,%1,%2,%3}, {%4,%5,%6,%7}, {%8,%9}, {%0,%1,%2,%3};"
                        : "+f"(acc[i][j][0]), "+f"(acc[i][j][1]),
                          "+f"(acc[i][j][2]), "+f"(acc[i][j][3])
                        : "r"(a[i][0]), "r"(a[i][1]), "r"(a[i][2]), "r"(a[i][3]),
                          "r"(b[j][0]), "r"(b[j][1]));
        }
        if (kb + 2 < KT) {
            int nst = st + 2; if (nst >= NSTAGE) nst -= NSTAGE;
            LOAD_STAGE(nst, kb + 2);
        }
        st++; if (st == NSTAGE) st = 0;
    }

    #pragma unroll
    for (int i = 0; i < 4; i++) {
        int row0 = bm + wm * 64 + i * 16 + gr;
        #pragma unroll
        for (int j = 0; j < 4; j++) {
            int col = bn + wn * 32 + j * 8 + gc * 2;
            float bx = 0.f, by = 0.f;
            if (bias) { bx = bias[col]; by = bias[col + 1]; }
            size_t o0 = (size_t)row0 * N + col;
            size_t o1 = (size_t)(row0 + 8) * N + col;
            float v0 = acc[i][j][0] + bx, v1 = acc[i][j][1] + by;
            float v2 = acc[i][j][2] + bx, v3 = acc[i][j][3] + by;
            if (r1) {
                float2 p0 = *(const float2*)(r1 + o0);
                float2 p1 = *(const float2*)(r1 + o1);
                v0 += p0.x; v1 += p0.y; v2 += p1.x; v3 += p1.y;
            }
            if (r2) {
                float2 p0 = *(const float2*)(r2 + o0);
                float2 p1 = *(const float2*)(r2 + o1);
                v0 += p0.x; v1 += p0.y; v2 += p1.x; v3 += p1.y;
            }
            if constexpr (sizeof(OutT) == 4) {
                *(float2*)((float*)Cout + o0) = make_float2(v0, v1);
                *(float2*)((float*)Cout + o1) = make_float2(v2, v3);
            } else {
                __nv_bfloat162 h0 = __floats2bfloat162_rn(v0, v1);
                __nv_bfloat162 h1 = __floats2bfloat162_rn(v2, v3);
                *(uint32_t*)((__nv_bfloat16*)Cout + o0) = *reinterpret_cast<uint32_t*>(&h0);
                *(uint32_t*)((__nv_bfloat16*)Cout + o1) = *reinterpret_cast<uint32_t*>(&h1);
            }
        }
    }
}

// ---------------- q softmax over tokens: per-(b,c) online partials ----------
__global__ void qsoft_part(const __nv_bfloat16* __restrict__ qkv)
{
    int b = blockIdx.x, ch = blockIdx.y, c = threadIdx.x;
    const __nv_bfloat16* p = qkv + ((size_t)(b * N_ + ch * 64)) * (3 * C_) + c;
    float m = -1e30f, s = 0.0f;
    for (int i = 0; i < 64; i++) {
        float v = __bfloat162float(p[(size_t)i * (3 * C_)]);
        float nm = fmaxf(m, v);
        s = s * __expf(m - nm) + __expf(v - nm);
        m = nm;
    }
    g_pm[(b * 64 + ch) * C_ + c] = m;
    g_ps[(b * 64 + ch) * C_ + c] = s;
}

__global__ void qsoft_comb()
{
    int idx = blockIdx.x * blockDim.x + threadIdx.x;
    if (idx >= B_ * C_) return;
    int b = idx >> 8, c = idx & 255;
    float M = -1e30f;
    for (int ch = 0; ch < 64; ch++) M = fmaxf(M, g_pm[(b * 64 + ch) * C_ + c]);
    float S = 0.0f;
    for (int ch = 0; ch < 64; ch++)
        S += g_ps[(b * 64 + ch) * C_ + c] * __expf(g_pm[(b * 64 + ch) * C_ + c] - M);
    g_cmax[idx] = M;
    g_cinv[idx] = 1.0f / S;
}

// ---------------- ctx = softmax_d(k)^T @ v ----------------------------------
__global__ __launch_bounds__(256) void ctx_kernel(const __nv_bfloat16* __restrict__ qkv)
{
    int chunk = blockIdx.x;
    int head  = blockIdx.y;
    int b     = blockIdx.z;
    __shared__ float ks[32][33];
    __shared__ float vs[32][33];
    int tid = threadIdx.x, lane = tid & 31, wp = tid >> 5;
    float acc[4] = {0.f, 0.f, 0.f, 0.f};
    for (int it = 0; it < 8; it++) {
        int nb = chunk * 256 + it * 32;
        #pragma unroll
        for (int j = 0; j < 8; j++) {
            int id = tid + 256 * j;
            int r = id >> 6, inner = id & 63;
            const __nv_bfloat16* src =
                qkv + ((size_t)(b * N_ + nb + r)) * (3 * C_) + C_ + head * D_;
            if (inner < 32) ks[r][inner] = __bfloat162float(src[inner]);
            else            vs[r][inner - 32] = __bfloat162float(src[C_ + inner - 32]);
        }
        __syncthreads();
        #pragma unroll
        for (int rr = 0; rr < 4; rr++) {
            int r = wp * 4 + rr;
            float v = ks[r][lane];
            float mx = v;
            #pragma unroll
            for (int o = 16; o; o >>= 1) mx = fmaxf(mx, __shfl_xor_sync(0xffffffffu, mx, o));
            float e = __expf(v - mx);
            float su = e;
            #pragma unroll
            for (int o = 16; o; o >>= 1) su += __shfl_xor_sync(0xffffffffu, su, o);
            ks[r][lane] = e / su;
        }
        __syncthreads();
        #pragma unroll
        for (int r = 0; r < 32; r++) {
            float vv = vs[r][lane];
            #pragma unroll
            for (int i = 0; i < 4; i++) acc[i] += ks[r][wp + 8 * i] * vv;
        }
        __syncthreads();
    }
    #pragma unroll
    for (int i = 0; i < 4; i++) {
        int e = wp + 8 * i;
        g_ctxp[(size_t)chunk * (B_ * HEADS_ * D_ * D_) +
               ((b * HEADS_ + head) * D_ + e) * D_ + lane] = acc[i];
    }
}

__global__ void ctx_comb()
{
    int idx = blockIdx.x * blockDim.x + threadIdx.x;
    if (idx >= B_ * HEADS_ * D_ * D_) return;
    float s = 0.0f;
    for (int ch = 0; ch < 16; ch++) s += g_ctxp[(size_t)ch * (B_ * HEADS_ * D_ * D_) + idx];
    g_ctx[idx] = s;
}

// ---------------- attn = softmax_N(q) @ ctx ---------------------------------
__global__ __launch_bounds__(256) void attn2(const __nv_bfloat16* __restrict__ qkv,
                                             __nv_bfloat16* __restrict__ out)
{
    int b = blockIdx.y;
    int base = blockIdx.x * 64;
    int h = threadIdx.x >> 5;
    int lane = threadIdx.x & 31;
    int ch = h * 32 + lane;

    float cm = g_cmax[b * C_ + ch];
    float ci = g_cinv[b * C_ + ch];
    float ctxr[32];
    #pragma unroll
    for (int e = 0; e < 32; e++)
        ctxr[e] = g_ctx[((b * HEADS_ + h) * D_ + e) * D_ + lane];

    const __nv_bfloat16* qbase = qkv + (size_t)(b * N_ + base) * (3 * C_) + ch;
    __nv_bfloat16* obase = out + (size_t)(b * N_ + base) * C_ + ch;
    for (int t = 0; t < 64; t++) {
        float q = __bfloat162float(qbase[(size_t)t * (3 * C_)]);
        float p = __expf(q - cm) * ci;
        float acc = 0.0f;
        #pragma unroll
        for (int e = 0; e < 32; e++)
            acc += __shfl_sync(0xffffffffu, p, e) * ctxr[e];
        obase[(size_t)t * C_] = __float2bfloat16_rn(acc);
    }
}

// ---------------- CSDA ------------------------------------------------------
__global__ void cpool_part(const float* __restrict__ x3)
{
    int b = blockIdx.x, ch = blockIdx.y, c = threadIdx.x;
    const float* p = x3 + ((size_t)(b * N_ + ch * 64)) * C_ + c;
    float s = 0.0f, m = -1e30f;
    for (int i = 0; i < 64; i++) {
        float v = p[(size_t)i * C_];
        s += v; m = fmaxf(m, v);
    }
    g_cps[(b * 64 + ch) * C_ + c] = s;
    g_cpm[(b * 64 + ch) * C_ + c] = m;
}

__global__ void cpool_comb()
{
    int idx = blockIdx.x * blockDim.x + threadIdx.x;
    if (idx >= B_ * C_) return;
    int b = idx >> 8, c = idx & 255;
    float s = 0.0f, m = -1e30f;
    for (int ch = 0; ch < 64; ch++) {
        s += g_cps[(b * 64 + ch) * C_ + c];
        m = fmaxf(m, g_cpm[(b * 64 + ch) * C_ + c]);
    }
    g_avg[idx] = s * (1.0f / N_);
    g_mx[idx] = m;
}

__global__ void ca_mlp(const float* __restrict__ w1, const float* __restrict__ w2)
{
    int b = blockIdx.x, t = threadIdx.x;
    __shared__ float hsum[16];
    if (t < 16) {
        float sa = 0.0f, sm = 0.0f;
        for (int c = 0; c < C_; c++) {
            float w = w1[t * C_ + c];
            sa += g_avg[b * C_ + c] * w;
            sm += g_mx[b * C_ + c] * w;
        }
        hsum[t] = fmaxf(sa, 0.0f) + fmaxf(sm, 0.0f);
    }
    __syncthreads();
    float acc = 0.0f;
    #pragma unroll
    for (int j = 0; j < 16; j++) acc += w2[t * 16 + j] * hsum[j];
    g_ca[b * C_ + t] = sigmf(acc);
}

__global__ void spool(const float* __restrict__ x3)
{
    int w = (blockIdx.x * blockDim.x + threadIdx.x) >> 5;
    int lane = threadIdx.x & 31;
    if (w >= ROWS_) return;
    int b = w >> 12;
    const float* r = x3 + (size_t)w * C_;
    const float* ca = g_ca + b * C_;
    float4 a = *(const float4*)(r + lane * 4);
    float4 c0 = *(const float4*)(ca + lane * 4);
    float4 bvals = *(const float4*)(r + 128 + lane * 4);
    float4 c1 = *(const float4*)(ca + 128 + lane * 4);
    float v0 = a.x * c0.x, v1 = a.y * c0.y, v2 = a.z * c0.z, v3 = a.w * c0.w;
    float v4 = bvals.x * c1.x, v5 = bvals.y * c1.y, v6 = bvals.z * c1.z, v7 = bvals.w * c1.w;
    float s = v0 + v1 + v2 + v3 + v4 + v5 + v6 + v7;
    float m = fmaxf(fmaxf(fmaxf(v0, v1), fmaxf(v2, v3)), fmaxf(fmaxf(v4, v5), fmaxf(v6, v7)));
    #pragma unroll
    for (int o = 16; o; o >>= 1) {
        s += __shfl_xor_sync(0xffffffffu, s, o);
        m = fmaxf(m, __shfl_xor_sync(0xffffffffu, m, o));
    }
    if (lane == 0) {
        g_sm[w] = s * (1.0f / C_);
        g_sx[w] = m;
    }
}

__global__ void conv7(const float* __restrict__ spw, const float* __restrict__ spb)
{
    int idx = blockIdx.x * blockDim.x + threadIdx.x;
    if (idx >= ROWS_) return;
    int b = idx >> 12, n = idx & 4095;
    int h = n >> 6, w = n & 63;
    float acc = spb[0];
    #pragma unroll
    for (int ch = 0; ch < 2; ch++) {
        const float* src = ch ? g_sx : g_sm;
        const float* wp = spw + ch * 49;
        for (int ky = 0; ky < 7; ky++) {
            int y = h + ky - 3;
            if ((unsigned)y >= 64u) continue;
            for (int kx = 0; kx < 7; kx++) {
                int x = w + kx - 3;
                if ((unsigned)x >= 64u) continue;
                acc += src[(b << 12) + (y << 6) + x] * wp[ky * 7 + kx];
            }
        }
    }
    g_sa[idx] = sigmf(acc);
}

__global__ void final_scale(const float* __restrict__ x3, float* __restrict__ out)
{
    int idx = blockIdx.x * blockDim.x + threadIdx.x;
    if (idx >= ROWS_ * 64) return;
    int c4 = idx & 63;
    int row = idx >> 6;
    int b = row >> 12;
    float4 v = *(const float4*)(x3 + (size_t)row * C_ + c4 * 4);
    float4 ca = *(const float4*)(g_ca + b * C_ + c4 * 4);
    float sa = g_sa[row];
    v.x *= ca.x * sa; v.y *= ca.y * sa; v.z *= ca.z * sa; v.w *= ca.w * sa;
    *(float4*)(out + (size_t)row * C_ + c4 * 4) = v;
}

// ---------------------------------------------------------------------------
extern "C" void kernel_launch(void* const* d_in, const int* in_sizes, int n_in,
                              void* d_out, int out_size)
{
    int p = (n_in >= 24 && in_sizes[1] == 1 && in_sizes[2] == 1) ? 3 : 1;
    const float* x      = (const float*)d_in[0];
    const float* n1_g   = (const float*)d_in[p + 0];
    const float* n1_b   = (const float*)d_in[p + 1];
    const float* sr_w   = (const float*)d_in[p + 2];
    const float* sr_b   = (const float*)d_in[p + 3];
    const float* an_g   = (const float*)d_in[p + 4];
    const float* an_b   = (const float*)d_in[p + 5];
    const float* qkv_w  = (const float*)d_in[p + 6];
    const float* proj_w = (const float*)d_in[p + 7];
    const float* proj_b = (const float*)d_in[p + 8];
    const float* n2_g   = (const float*)d_in[p + 9];
    const float* n2_b   = (const float*)d_in[p + 10];
    const float* fc1_w  = (const float*)d_in[p + 11];
    const float* fc1_b  = (const float*)d_in[p + 12];
    const float* dw_w   = (const float*)d_in[p + 13];
    const float* dw_b   = (const float*)d_in[p + 14];
    const float* fc2_w  = (const float*)d_in[p + 15];
    const float* fc2_b  = (const float*)d_in[p + 16];
    const float* ca_w1  = (const float*)d_in[p + 17];
    const float* ca_w2  = (const float*)d_in[p + 18];
    const float* sp_w   = (const float*)d_in[p + 19];
    const float* sp_b   = (const float*)d_in[p + 20];
    float* out = (float*)d_out;

    float *pxn, *pb1, *pb2;
    __nv_bfloat16 *pqkv16, *pa16, *ph16a, *ph16b, *pw16;
    cudaGetSymbolAddress((void**)&pxn,    g_xn);
    cudaGetSymbolAddress((void**)&pb1,    g_b1);
    cudaGetSymbolAddress((void**)&pb2,    g_b2);
    cudaGetSymbolAddress((void**)&pqkv16, g_qkv16);
    cudaGetSymbolAddress((void**)&pa16,   g_a16);
    cudaGetSymbolAddress((void**)&ph16a,  g_h16a);
    cudaGetSymbolAddress((void**)&ph16b,  g_h16b);
    cudaGetSymbolAddress((void**)&pw16,   g_w16);

    const int TPB = 256;
    const int GEMM_SMEM = NSTAGE * SSTG * 2;   // 98304 bytes
    cudaFuncSetAttribute(gemm_bf16<float>, cudaFuncAttributeMaxDynamicSharedMemorySize,
                         GEMM_SMEM);
    cudaFuncSetAttribute(gemm_bf16<__nv_bfloat16>, cudaFuncAttributeMaxDynamicSharedMemorySize,
                         GEMM_SMEM);

    // 0. bf16 weight conversion (one kernel)
    f2bf_all<<<(393216 + TPB - 1) / TPB, TPB>>>(qkv_w, proj_w, fc1_w, fc2_w, pw16);

    // 1. xn = LN1(x)
    ln256<float><<<ROWS_ * 32 / TPB, TPB>>>(x, pxn, n1_g, n1_b);
    // 2+3. xa16 = bf16(xn + gelu(LN_act(dwconv3(xn))))  (fused)
    sr_fuse<<<ROWS_, TPB>>>(pxn, pa16, sr_w, sr_b, an_g, an_b);
    // 4. qkv = xa @ qkv_w^T  (bf16 out)
    {
        dim3 g(3 * C_ / 128, ROWS_ / 128);
        gemm_bf16<__nv_bfloat16><<<g, TPB, GEMM_SMEM>>>(pa16, pw16 + W16_QKV, pqkv16,
                                                        ROWS_, 3 * C_, C_, nullptr, nullptr, nullptr);
    }
    // 5. q column-softmax stats
    {
        dim3 g(B_, 64);
        qsoft_part<<<g, TPB>>>(pqkv16);
        qsoft_comb<<<(B_ * C_ + TPB - 1) / TPB, TPB>>>();
    }
    // 6. ctx = softmax_d(k)^T v
    {
        dim3 g(16, HEADS_, B_);
        ctx_kernel<<<g, TPB>>>(pqkv16);
        ctx_comb<<<(B_ * HEADS_ * D_ * D_ + TPB - 1) / TPB, TPB>>>();
    }
    // 7. attn = softmax_N(q) @ ctx -> a16 (bf16)
    {
        dim3 g(N_ / 64, B_);
        attn2<<<g, TPB>>>(pqkv16, pa16);
    }
    // 8. x2 = x + attn @ proj_w^T + proj_b + xn -> b1
    {
        dim3 g(C_ / 128, ROWS_ / 128);
        gemm_bf16<float><<<g, TPB, GEMM_SMEM>>>(pa16, pw16 + W16_PROJ, pb1,
                                                ROWS_, C_, C_, proj_b, x, pxn);
    }
    // 9. ln2(x2) -> a16 (bf16)
    ln256<__nv_bfloat16><<<ROWS_ * 32 / TPB, TPB>>>(pb1, pa16, n2_g, n2_b);
    // 10. fc1 -> h16a (bf16)
    {
        dim3 g(HID_ / 128, ROWS_ / 128);
        gemm_bf16<__nv_bfloat16><<<g, TPB, GEMM_SMEM>>>(pa16, pw16 + W16_FC1, ph16a,
                                                        ROWS_, HID_, C_, fc1_b, nullptr, nullptr);
    }
    // 11. dwconv + gelu (bf16, sliding window) -> h16b
    {
        dim3 g(HID_ / 4 / 16, 64, B_);
        dwconv3_bf16_v2<<<g, TPB>>>(ph16a, ph16b, dw_w, dw_b);
    }
    // 12. x3 = x2 + gelu_dw @ fc2_w^T + fc2_b -> b2
    {
        dim3 g(C_ / 128, ROWS_ / 128);
        gemm_bf16<float><<<g, TPB, GEMM_SMEM>>>(ph16b, pw16 + W16_FC2, pb2,
                                                ROWS_, C_, HID_, fc2_b, pb1, nullptr);
    }
    // 13. channel pools
    {
        dim3 g(B_, 64);
        cpool_part<<<g, TPB>>>(pb2);
        cpool_comb<<<(B_ * C_ + TPB - 1) / TPB, TPB>>>();
    }
    // 14. channel attention MLP
    ca_mlp<<<B_, TPB>>>(ca_w1, ca_w2);
    // 15. spatial pools of x3*ca
    spool<<<ROWS_ * 32 / TPB, TPB>>>(pb2);
    // 16. 7x7 spatial conv -> sa
    conv7<<<(ROWS_ + TPB - 1) / TPB, TPB>>>(sp_w, sp_b);
    // 17. out = x3 * ca * sa
    final_scale<<<(ROWS_ * 64 + TPB - 1) / TPB, TPB>>>(pb2, out);
}

// round 15
// speedup vs baseline: 1.0915x; 1.0590x over previous
#include <cuda_runtime.h>
#include <cuda_bf16.h>
#include <math.h>
#include <stdint.h>

// Problem constants
#define B_    16
#define N_    4096
#define C_    256
#define HEADS_ 8
#define D_    32
#define HID_  1024
#define ROWS_ 65536          // B_*N_

// ---------------- scratch (device globals; no allocation allowed) ----------
__device__ float g_xn  [ROWS_ * C_];           // norm1(x)
__device__ float g_b1  [ROWS_ * C_];           // x2
__device__ float g_b2  [ROWS_ * C_];           // x3
__device__ __nv_bfloat16 g_qkv16[ROWS_ * 3 * C_]; // qkv (bf16)
__device__ __nv_bfloat16 g_a16 [ROWS_ * C_];   // xa / attn / ln2 (bf16, reused)
__device__ __nv_bfloat16 g_h16a[ROWS_ * HID_]; // fc1 out (bf16)
__device__ __nv_bfloat16 g_h16b[ROWS_ * HID_]; // dwconv+gelu out (bf16)
__device__ __nv_bfloat16 g_w16 [786432];       // bf16 weights (qkv|proj|fc1|fc2)
#define W16_QKV  0
#define W16_PROJ 196608
#define W16_FC1  262144
#define W16_FC2  524288
__device__ float g_pm  [B_ * 64 * C_];
__device__ float g_ps  [B_ * 64 * C_];
__device__ float g_cmax[B_ * C_];
__device__ float g_cinv[B_ * C_];
__device__ float g_ctxp[16 * B_ * HEADS_ * D_ * D_];
__device__ float g_ctx [B_ * HEADS_ * D_ * D_];
__device__ float g_cps [B_ * 64 * C_];
__device__ float g_cpm [B_ * 64 * C_];
__device__ float g_avg [B_ * C_];
__device__ float g_mx  [B_ * C_];
__device__ float g_ca  [B_ * C_];
__device__ float g_sm  [ROWS_];
__device__ float g_sx  [ROWS_];
__device__ float g_sa  [ROWS_];

__device__ __forceinline__ float geluf(float x) {
    return 0.5f * x * (1.0f + erff(x * 0.70710678118654752440f));
}
__device__ __forceinline__ float sigmf(float x) {
    return 1.0f / (1.0f + __expf(-x));
}
__device__ __forceinline__ void store8(float* p, float4 v) { *(float4*)p = v; }
__device__ __forceinline__ void store8(__nv_bfloat16* p, float4 v) {
    __nv_bfloat162 h0 = __floats2bfloat162_rn(v.x, v.y);
    __nv_bfloat162 h1 = __floats2bfloat162_rn(v.z, v.w);
    uint2 u;
    u.x = *reinterpret_cast<uint32_t*>(&h0);
    u.y = *reinterpret_cast<uint32_t*>(&h1);
    *(uint2*)p = u;
}

// ---------------- fp32 -> bf16 weight conversion (all 4 weights, 1 kernel) --
__global__ void f2bf_all(const float* __restrict__ s0, const float* __restrict__ s1,
                         const float* __restrict__ s2, const float* __restrict__ s3,
                         __nv_bfloat16* __restrict__ dst)
{
    int i = blockIdx.x * blockDim.x + threadIdx.x;
    if (i >= 393216) return;
    int e = i * 2;
    const float* src;
    int off;
    if (e < W16_PROJ)      { src = s0; off = e; }
    else if (e < W16_FC1)  { src = s1; off = e - W16_PROJ; }
    else if (e < W16_FC2)  { src = s2; off = e - W16_FC1; }
    else                   { src = s3; off = e - W16_FC2; }
    float2 v = *(const float2*)(src + off);
    __nv_bfloat162 h = __floats2bfloat162_rn(v.x, v.y);
    *(uint32_t*)(dst + e) = *reinterpret_cast<uint32_t*>(&h);
}

// ---------------- LayerNorm (256 wide), one warp per row --------------------
template <typename OutT>
__global__ void ln256(const float* __restrict__ in, OutT* __restrict__ out,
                      const float* __restrict__ g, const float* __restrict__ bt)
{
    int w = (blockIdx.x * blockDim.x + threadIdx.x) >> 5;
    int lane = threadIdx.x & 31;
    if (w >= ROWS_) return;
    const float* r = in + (size_t)w * C_;
    float4 a = *(const float4*)(r + lane * 4);
    float4 b = *(const float4*)(r + 128 + lane * 4);
    float s = a.x + a.y + a.z + a.w + b.x + b.y + b.z + b.w;
    float q = a.x*a.x + a.y*a.y + a.z*a.z + a.w*a.w
            + b.x*b.x + b.y*b.y + b.z*b.z + b.w*b.w;
    #pragma unroll
    for (int o = 16; o; o >>= 1) {
        s += __shfl_xor_sync(0xffffffffu, s, o);
        q += __shfl_xor_sync(0xffffffffu, q, o);
    }
    float mean = s * (1.0f / C_);
    float inv = rsqrtf(q * (1.0f / C_) - mean * mean + 1e-5f);
    float4 g0 = *(const float4*)(g + lane * 4);
    float4 g1 = *(const float4*)(g + 128 + lane * 4);
    float4 b0 = *(const float4*)(bt + lane * 4);
    float4 b1 = *(const float4*)(bt + 128 + lane * 4);
    float4 o0, o1;
    o0.x = (a.x - mean) * inv * g0.x + b0.x;
    o0.y = (a.y - mean) * inv * g0.y + b0.y;
    o0.z = (a.z - mean) * inv * g0.z + b0.z;
    o0.w = (a.w - mean) * inv * g0.w + b0.w;
    o1.x = (b.x - mean) * inv * g1.x + b1.x;
    o1.y = (b.y - mean) * inv * g1.y + b1.y;
    o1.z = (b.z - mean) * inv * g1.z + b1.z;
    o1.w = (b.w - mean) * inv * g1.w + b1.w;
    OutT* po = out + (size_t)w * C_;
    store8(po + lane * 4, o0);
    store8(po + 128 + lane * 4, o1);
}

// --------- fused SR: smem-tiled dwconv3(xn) -> LN -> gelu -> +xn -> bf16 ----
// block = 4x4 output tokens; tile = 6x6 tokens x 256 ch fp32 in smem.
// 256 thr = 16 tokens x 16 lanes; thread handles channels c = lane + 16*ci.
__global__ __launch_bounds__(256)
void sr_fuse_v2(const float* __restrict__ xn, __nv_bfloat16* __restrict__ out,
                const float* __restrict__ sw, const float* __restrict__ sb,
                const float* __restrict__ ag, const float* __restrict__ ab)
{
    __shared__ float tile[36][272];     // token stride 272 -> conflict-free
    __shared__ float wk[9 * 256];       // wk[k][c] = sw[c*9+k]

    int tid = threadIdx.x;
    int w0 = blockIdx.x * 4;
    int h0 = blockIdx.y * 4;
    int b  = blockIdx.z;

    // load 6x6 token patch (halo zero-filled), 2304 float4 over 9 iters
    #pragma unroll
    for (int i = 0; i < 9; i++) {
        int idx = tid + 256 * i;
        int tok = idx >> 6, part = idx & 63;
        int tr = tok / 6, tc = tok - tr * 6;
        int h = h0 + tr - 1, w = w0 + tc - 1;
        float4 v = make_float4(0.f, 0.f, 0.f, 0.f);
        if ((unsigned)h < 64u && (unsigned)w < 64u)
            v = *(const float4*)(xn + ((size_t)(b * N_ + (h << 6) + w)) * C_ + part * 4);
        *(float4*)(&tile[tok][part * 4]) = v;
    }
    // transposed weights
    #pragma unroll
    for (int k = 0; k < 9; k++)
        wk[k * 256 + tid] = sw[tid * 9 + k];
    __syncthreads();

    int tl = tid >> 4;                   // local token 0..15
    int ty = tl >> 2, tx = tl & 3;
    int c0 = tid & 15;
    int base_tok = ty * 6 + tx;          // top-left of 3x3 window

    float accs[16];
    float s = 0.f, q = 0.f;
    #pragma unroll
    for (int ci = 0; ci < 16; ci++) {
        int c = c0 + (ci << 4);
        float a = sb[c];
        #pragma unroll
        for (int dy = 0; dy < 3; dy++)
            #pragma unroll
            for (int dx = 0; dx < 3; dx++)
                a += tile[base_tok + dy * 6 + dx][c] * wk[(dy * 3 + dx) * 256 + c];
        accs[ci] = a;
        s += a;
        q += a * a;
    }
    // reduce over the 16 lanes of this token
    #pragma unroll
    for (int o = 8; o; o >>= 1) {
        s += __shfl_xor_sync(0xffffffffu, s, o);
        q += __shfl_xor_sync(0xffffffffu, q, o);
    }
    float mean = s * (1.0f / C_);
    float inv = rsqrtf(q * (1.0f / C_) - mean * mean + 1e-5f);

    int ctr = (ty + 1) * 6 + (tx + 1);
    size_t n = (size_t)(b * N_ + ((h0 + ty) << 6) + (w0 + tx));
    __nv_bfloat16* po = out + n * C_;
    #pragma unroll
    for (int ci = 0; ci < 16; ci++) {
        int c = c0 + (ci << 4);
        float v = (accs[ci] - mean) * inv * ag[c] + ab[c];
        float xa = tile[ctr][c] + geluf(v);
        po[c] = __float2bfloat16_rn(xa);
    }
}

// --------- depthwise 3x3 bf16 + gelu, 4-token sliding window ----------------
__global__ __launch_bounds__(256)
void dwconv3_bf16_v2(const __nv_bfloat16* __restrict__ in,
                     __nv_bfloat16* __restrict__ out,
                     const float* __restrict__ w, const float* __restrict__ bias)
{
    const int CH = HID_;
    int tid = threadIdx.x;
    int c0 = (blockIdx.x * 16 + (tid & 15)) * 4;
    int h  = blockIdx.y;
    int b  = blockIdx.z;
    int w0 = (tid >> 4) * 4;

    float wr[4][9];
    #pragma unroll
    for (int i = 0; i < 4; i++)
        #pragma unroll
        for (int k = 0; k < 9; k++)
            wr[i][k] = w[(c0 + i) * 9 + k];

    float acc[4][4];
    #pragma unroll
    for (int t = 0; t < 4; t++)
        #pragma unroll
        for (int i = 0; i < 4; i++)
            acc[t][i] = bias[c0 + i];

    #pragma unroll
    for (int dy = -1; dy <= 1; dy++) {
        int hh = h + dy;
        if ((unsigned)hh >= 64u) continue;
        const __nv_bfloat16* rowp = in + ((size_t)(b * N_ + (hh << 6))) * CH + c0;
        #pragma unroll
        for (int wx = -1; wx <= 4; wx++) {
            int ww = w0 + wx;
            if ((unsigned)ww >= 64u) continue;
            uint2 raw = *(const uint2*)(rowp + (size_t)ww * CH);
            float2 f0 = __bfloat1622float2(*reinterpret_cast<__nv_bfloat162*>(&raw.x));
            float2 f1 = __bfloat1622float2(*reinterpret_cast<__nv_bfloat162*>(&raw.y));
            float f[4] = {f0.x, f0.y, f1.x, f1.y};
            #pragma unroll
            for (int t = 0; t < 4; t++) {
                int kx = wx - t;
                if (kx < -1 || kx > 1) continue;
                int k = (dy + 1) * 3 + kx + 1;
                #pragma unroll
                for (int i = 0; i < 4; i++)
                    acc[t][i] += f[i] * wr[i][k];
            }
        }
    }
    #pragma unroll
    for (int t = 0; t < 4; t++) {
        float4 o = make_float4(geluf(acc[t][0]), geluf(acc[t][1]),
                               geluf(acc[t][2]), geluf(acc[t][3]));
        store8(out + ((size_t)(b * N_ + (h << 6) + w0 + t)) * CH + c0, o);
    }
}

// -------- BF16 GEMM, 3-stage cp.async pipeline, XOR-swizzled smem -----------
// tile 128x128x64; 8 warps (2m x 4n); warp 64x32 via m16n8k16 + ldmatrix.
#define SSTG 16384                 // bytes per stage per matrix
#define NSTAGE 3

__device__ __forceinline__ void cp16(uint32_t d, const void* s) {
    asm volatile("cp.async.cg.shared.global [%0], [%1], 16;" :: "r"(d), "l"(s));
}

template <typename OutT>
__global__ __launch_bounds__(256, 2)
void gemm_bf16(const __nv_bfloat16* __restrict__ A, const __nv_bfloat16* __restrict__ W,
               OutT* __restrict__ Cout, int M, int N, int K,
               const float* __restrict__ bias,
               const float* __restrict__ r1, const float* __restrict__ r2)
{
    extern __shared__ __nv_bfloat16 sh16[];
    uint32_t sA0 = (uint32_t)__cvta_generic_to_shared(sh16);
    uint32_t sB0 = sA0 + NSTAGE * SSTG;

    int tid = threadIdx.x;
    int warp = tid >> 5, lane = tid & 31;
    int wm = warp >> 2, wn = warp & 3;
    int bm = blockIdx.y * 128, bn = blockIdx.x * 128;
    int gr = lane >> 2, gc = lane & 3;

    float acc[4][4][4];
    #pragma unroll
    for (int i = 0; i < 4; i++)
        #pragma unroll
        for (int j = 0; j < 4; j++)
            #pragma unroll
            for (int q = 0; q < 4; q++) acc[i][j][q] = 0.0f;

    int KT = K >> 6;

    int ldr = tid >> 3;
    int chk = tid & 7;
    uint32_t swd = (uint32_t)(ldr * 128 + ((chk ^ (ldr & 7)) << 4));
    const __nv_bfloat16* Abase = A + (size_t)(bm + ldr) * K + chk * 8;
    const __nv_bfloat16* Wbase = W + (size_t)(bn + ldr) * K + chk * 8;

    #define LOAD_STAGE(st, kb) do {                                            \
        uint32_t so = (st) * SSTG + swd;                                       \
        size_t go = (size_t)(kb) * 64;                                         \
        _Pragma("unroll")                                                      \
        for (int it = 0; it < 4; it++) {                                       \
            cp16(sA0 + so + it * 4096, Abase + (size_t)(it * 32) * K + go);    \
            cp16(sB0 + so + it * 4096, Wbase + (size_t)(it * 32) * K + go);    \
        }                                                                      \
        asm volatile("cp.async.commit_group;");                                \
    } while (0)

    LOAD_STAGE(0, 0);
    if (KT > 1) LOAD_STAGE(1, 1);

    int rA = wm * 64 + (lane & 15);
    int cAx = lane >> 4;
    int sa7 = rA & 7;
    int rB = wn * 32 + (lane & 7);
    int cBx = (lane >> 3) & 1;
    int sb7 = rB & 7;

    uint32_t caO[4], cbO[4];
    #pragma unroll
    for (int ks = 0; ks < 4; ks++) {
        caO[ks] = (uint32_t)(((ks * 2 + cAx) ^ sa7) << 4);
        cbO[ks] = (uint32_t)(((ks * 2 + cBx) ^ sb7) << 4);
    }
    uint32_t rAb[4], rBb[4];
    #pragma unroll
    for (int i = 0; i < 4; i++) rAb[i] = (uint32_t)((rA + i * 16) * 128);
    #pragma unroll
    for (int j = 0; j < 4; j++) rBb[j] = (uint32_t)((rB + j * 8) * 128);

    int st = 0;
    for (int kb = 0; kb < KT; kb++) {
        asm volatile("cp.async.wait_group 1;");
        __syncthreads();

        uint32_t stA = sA0 + st * SSTG;
        uint32_t stB = sB0 + st * SSTG;
        #pragma unroll
        for (int ks = 0; ks < 4; ks++) {
            uint32_t a[4][4], b[4][2];
            #pragma unroll
            for (int i = 0; i < 4; i++) {
                uint32_t addr = stA + rAb[i] + caO[ks];
                asm volatile(
                    "ldmatrix.sync.aligned.m8n8.x4.shared.b16 {%0,%1,%2,%3}, [%4];"
                    : "=r"(a[i][0]), "=r"(a[i][1]), "=r"(a[i][2]), "=r"(a[i][3])
                    : "r"(addr));
            }
            #pragma unroll
            for (int j = 0; j < 4; j++) {
                uint32_t addr = stB + rBb[j] + cbO[ks];
                asm volatile(
                    "ldmatrix.sync.aligned.m8n8.x2.shared.b16 {%0,%1}, [%2];"
                    : "=r"(b[j][0]), "=r"(b[j][1])
                    : "r"(addr));
            }
            #pragma unroll
            for (int i = 0; i < 4; i++)
                #pragma unroll
                for (int j = 0; j < 4; j++)
                    asm volatile(
                        "mma.sync.aligned.m16n8k16.row.col.f32.bf16.bf16.f32 "
                        "{%0,%1,%2,%3}, {%4,%5,%6,%7}, {%8,%9}, {%0,%1,%2,%3};"
                        : "+f"(acc[i][j][0]), "+f"(acc[i][j][1]),
                          "+f"(acc[i][j][2]), "+f"(acc[i][j][3])
                        : "r"(a[i][0]), "r"(a[i][1]), "r"(a[i][2]), "r"(a[i][3]),
                          "r"(b[j][0]), "r"(b[j][1]));
        }
        if (kb + 2 < KT) {
            int nst = st + 2; if (nst >= NSTAGE) nst -= NSTAGE;
            LOAD_STAGE(nst, kb + 2);
        }
        st++; if (st == NSTAGE) st = 0;
    }

    #pragma unroll
    for (int i = 0; i < 4; i++) {
        int row0 = bm + wm * 64 + i * 16 + gr;
        #pragma unroll
        for (int j = 0; j < 4; j++) {
            int col = bn + wn * 32 + j * 8 + gc * 2;
            float bx = 0.f, by = 0.f;
            if (bias) { bx = bias[col]; by = bias[col + 1]; }
            size_t o0 = (size_t)row0 * N + col;
            size_t o1 = (size_t)(row0 + 8) * N + col;
            float v0 = acc[i][j][0] + bx, v1 = acc[i][j][1] + by;
            float v2 = acc[i][j][2] + bx, v3 = acc[i][j][3] + by;
            if (r1) {
                float2 p0 = *(const float2*)(r1 + o0);
                float2 p1 = *(const float2*)(r1 + o1);
                v0 += p0.x; v1 += p0.y; v2 += p1.x; v3 += p1.y;
            }
            if (r2) {
                float2 p0 = *(const float2*)(r2 + o0);
                float2 p1 = *(const float2*)(r2 + o1);
                v0 += p0.x; v1 += p0.y; v2 += p1.x; v3 += p1.y;
            }
            if constexpr (sizeof(OutT) == 4) {
                *(float2*)((float*)Cout + o0) = make_float2(v0, v1);
                *(float2*)((float*)Cout + o1) = make_float2(v2, v3);
            } else {
                __nv_bfloat162 h0 = __floats2bfloat162_rn(v0, v1);
                __nv_bfloat162 h1 = __floats2bfloat162_rn(v2, v3);
                *(uint32_t*)((__nv_bfloat16*)Cout + o0) = *reinterpret_cast<uint32_t*>(&h0);
                *(uint32_t*)((__nv_bfloat16*)Cout + o1) = *reinterpret_cast<uint32_t*>(&h1);
            }
        }
    }
}

// ---------------- q softmax over tokens: per-(b,c) online partials ----------
__global__ void qsoft_part(const __nv_bfloat16* __restrict__ qkv)
{
    int b = blockIdx.x, ch = blockIdx.y, c = threadIdx.x;
    const __nv_bfloat16* p = qkv + ((size_t)(b * N_ + ch * 64)) * (3 * C_) + c;
    float m = -1e30f, s = 0.0f;
    for (int i = 0; i < 64; i++) {
        float v = __bfloat162float(p[(size_t)i * (3 * C_)]);
        float nm = fmaxf(m, v);
        s = s * __expf(m - nm) + __expf(v - nm);
        m = nm;
    }
    g_pm[(b * 64 + ch) * C_ + c] = m;
    g_ps[(b * 64 + ch) * C_ + c] = s;
}

__global__ void qsoft_comb()
{
    int idx = blockIdx.x * blockDim.x + threadIdx.x;
    if (idx >= B_ * C_) return;
    int b = idx >> 8, c = idx & 255;
    float M = -1e30f;
    for (int ch = 0; ch < 64; ch++) M = fmaxf(M, g_pm[(b * 64 + ch) * C_ + c]);
    float S = 0.0f;
    for (int ch = 0; ch < 64; ch++)
        S += g_ps[(b * 64 + ch) * C_ + c] * __expf(g_pm[(b * 64 + ch) * C_ + c] - M);
    g_cmax[idx] = M;
    g_cinv[idx] = 1.0f / S;
}

// ---------------- ctx = softmax_d(k)^T @ v ----------------------------------
__global__ __launch_bounds__(256) void ctx_kernel(const __nv_bfloat16* __restrict__ qkv)
{
    int chunk = blockIdx.x;
    int head  = blockIdx.y;
    int b     = blockIdx.z;
    __shared__ float ks[32][33];
    __shared__ float vs[32][33];
    int tid = threadIdx.x, lane = tid & 31, wp = tid >> 5;
    float acc[4] = {0.f, 0.f, 0.f, 0.f};
    for (int it = 0; it < 8; it++) {
        int nb = chunk * 256 + it * 32;
        #pragma unroll
        for (int j = 0; j < 8; j++) {
            int id = tid + 256 * j;
            int r = id >> 6, inner = id & 63;
            const __nv_bfloat16* src =
                qkv + ((size_t)(b * N_ + nb + r)) * (3 * C_) + C_ + head * D_;
            if (inner < 32) ks[r][inner] = __bfloat162float(src[inner]);
            else            vs[r][inner - 32] = __bfloat162float(src[C_ + inner - 32]);
        }
        __syncthreads();
        #pragma unroll
        for (int rr = 0; rr < 4; rr++) {
            int r = wp * 4 + rr;
            float v = ks[r][lane];
            float mx = v;
            #pragma unroll
            for (int o = 16; o; o >>= 1) mx = fmaxf(mx, __shfl_xor_sync(0xffffffffu, mx, o));
            float e = __expf(v - mx);
            float su = e;
            #pragma unroll
            for (int o = 16; o; o >>= 1) su += __shfl_xor_sync(0xffffffffu, su, o);
            ks[r][lane] = e / su;
        }
        __syncthreads();
        #pragma unroll
        for (int r = 0; r < 32; r++) {
            float vv = vs[r][lane];
            #pragma unroll
            for (int i = 0; i < 4; i++) acc[i] += ks[r][wp + 8 * i] * vv;
        }
        __syncthreads();
    }
    #pragma unroll
    for (int i = 0; i < 4; i++) {
        int e = wp + 8 * i;
        g_ctxp[(size_t)chunk * (B_ * HEADS_ * D_ * D_) +
               ((b * HEADS_ + head) * D_ + e) * D_ + lane] = acc[i];
    }
}

__global__ void ctx_comb()
{
    int idx = blockIdx.x * blockDim.x + threadIdx.x;
    if (idx >= B_ * HEADS_ * D_ * D_) return;
    float s = 0.0f;
    for (int ch = 0; ch < 16; ch++) s += g_ctxp[(size_t)ch * (B_ * HEADS_ * D_ * D_) + idx];
    g_ctx[idx] = s;
}

// ---------------- attn = softmax_N(q) @ ctx ---------------------------------
__global__ __launch_bounds__(256) void attn2(const __nv_bfloat16* __restrict__ qkv,
                                             __nv_bfloat16* __restrict__ out)
{
    int b = blockIdx.y;
    int base = blockIdx.x * 64;
    int h = threadIdx.x >> 5;
    int lane = threadIdx.x & 31;
    int ch = h * 32 + lane;

    float cm = g_cmax[b * C_ + ch];
    float ci = g_cinv[b * C_ + ch];
    float ctxr[32];
    #pragma unroll
    for (int e = 0; e < 32; e++)
        ctxr[e] = g_ctx[((b * HEADS_ + h) * D_ + e) * D_ + lane];

    const __nv_bfloat16* qbase = qkv + (size_t)(b * N_ + base) * (3 * C_) + ch;
    __nv_bfloat16* obase = out + (size_t)(b * N_ + base) * C_ + ch;
    for (int t = 0; t < 64; t++) {
        float q = __bfloat162float(qbase[(size_t)t * (3 * C_)]);
        float p = __expf(q - cm) * ci;
        float acc = 0.0f;
        #pragma unroll
        for (int e = 0; e < 32; e++)
            acc += __shfl_sync(0xffffffffu, p, e) * ctxr[e];
        obase[(size_t)t * C_] = __float2bfloat16_rn(acc);
    }
}

// ---------------- CSDA ------------------------------------------------------
__global__ void cpool_part(const float* __restrict__ x3)
{
    int b = blockIdx.x, ch = blockIdx.y, c = threadIdx.x;
    const float* p = x3 + ((size_t)(b * N_ + ch * 64)) * C_ + c;
    float s = 0.0f, m = -1e30f;
    for (int i = 0; i < 64; i++) {
        float v = p[(size_t)i * C_];
        s += v; m = fmaxf(m, v);
    }
    g_cps[(b * 64 + ch) * C_ + c] = s;
    g_cpm[(b * 64 + ch) * C_ + c] = m;
}

__global__ void cpool_comb()
{
    int idx = blockIdx.x * blockDim.x + threadIdx.x;
    if (idx >= B_ * C_) return;
    int b = idx >> 8, c = idx & 255;
    float s = 0.0f, m = -1e30f;
    for (int ch = 0; ch < 64; ch++) {
        s += g_cps[(b * 64 + ch) * C_ + c];
        m = fmaxf(m, g_cpm[(b * 64 + ch) * C_ + c]);
    }
    g_avg[idx] = s * (1.0f / N_);
    g_mx[idx] = m;
}

__global__ void ca_mlp(const float* __restrict__ w1, const float* __restrict__ w2)
{
    int b = blockIdx.x, t = threadIdx.x;
    __shared__ float hsum[16];
    if (t < 16) {
        float sa = 0.0f, sm = 0.0f;
        for (int c = 0; c < C_; c++) {
            float w = w1[t * C_ + c];
            sa += g_avg[b * C_ + c] * w;
            sm += g_mx[b * C_ + c] * w;
        }
        hsum[t] = fmaxf(sa, 0.0f) + fmaxf(sm, 0.0f);
    }
    __syncthreads();
    float acc = 0.0f;
    #pragma unroll
    for (int j = 0; j < 16; j++) acc += w2[t * 16 + j] * hsum[j];
    g_ca[b * C_ + t] = sigmf(acc);
}

__global__ void spool(const float* __restrict__ x3)
{
    int w = (blockIdx.x * blockDim.x + threadIdx.x) >> 5;
    int lane = threadIdx.x & 31;
    if (w >= ROWS_) return;
    int b = w >> 12;
    const float* r = x3 + (size_t)w * C_;
    const float* ca = g_ca + b * C_;
    float4 a = *(const float4*)(r + lane * 4);
    float4 c0 = *(const float4*)(ca + lane * 4);
    float4 bvals = *(const float4*)(r + 128 + lane * 4);
    float4 c1 = *(const float4*)(ca + 128 + lane * 4);
    float v0 = a.x * c0.x, v1 = a.y * c0.y, v2 = a.z * c0.z, v3 = a.w * c0.w;
    float v4 = bvals.x * c1.x, v5 = bvals.y * c1.y, v6 = bvals.z * c1.z, v7 = bvals.w * c1.w;
    float s = v0 + v1 + v2 + v3 + v4 + v5 + v6 + v7;
    float m = fmaxf(fmaxf(fmaxf(v0, v1), fmaxf(v2, v3)), fmaxf(fmaxf(v4, v5), fmaxf(v6, v7)));
    #pragma unroll
    for (int o = 16; o; o >>= 1) {
        s += __shfl_xor_sync(0xffffffffu, s, o);
        m = fmaxf(m, __shfl_xor_sync(0xffffffffu, m, o));
    }
    if (lane == 0) {
        g_sm[w] = s * (1.0f / C_);
        g_sx[w] = m;
    }
}

__global__ void conv7(const float* __restrict__ spw, const float* __restrict__ spb)
{
    int idx = blockIdx.x * blockDim.x + threadIdx.x;
    if (idx >= ROWS_) return;
    int b = idx >> 12, n = idx & 4095;
    int h = n >> 6, w = n & 63;
    float acc = spb[0];
    #pragma unroll
    for (int ch = 0; ch < 2; ch++) {
        const float* src = ch ? g_sx : g_sm;
        const float* wp = spw + ch * 49;
        for (int ky = 0; ky < 7; ky++) {
            int y = h + ky - 3;
            if ((unsigned)y >= 64u) continue;
            for (int kx = 0; kx < 7; kx++) {
                int x = w + kx - 3;
                if ((unsigned)x >= 64u) continue;
                acc += src[(b << 12) + (y << 6) + x] * wp[ky * 7 + kx];
            }
        }
    }
    g_sa[idx] = sigmf(acc);
}

__global__ void final_scale(const float* __restrict__ x3, float* __restrict__ out)
{
    int idx = blockIdx.x * blockDim.x + threadIdx.x;
    if (idx >= ROWS_ * 64) return;
    int c4 = idx & 63;
    int row = idx >> 6;
    int b = row >> 12;
    float4 v = *(const float4*)(x3 + (size_t)row * C_ + c4 * 4);
    float4 ca = *(const float4*)(g_ca + b * C_ + c4 * 4);
    float sa = g_sa[row];
    v.x *= ca.x * sa; v.y *= ca.y * sa; v.z *= ca.z * sa; v.w *= ca.w * sa;
    *(float4*)(out + (size_t)row * C_ + c4 * 4) = v;
}

// ---------------------------------------------------------------------------
extern "C" void kernel_launch(void* const* d_in, const int* in_sizes, int n_in,
                              void* d_out, int out_size)
{
    int p = (n_in >= 24 && in_sizes[1] == 1 && in_sizes[2] == 1) ? 3 : 1;
    const float* x      = (const float*)d_in[0];
    const float* n1_g   = (const float*)d_in[p + 0];
    const float* n1_b   = (const float*)d_in[p + 1];
    const float* sr_w   = (const float*)d_in[p + 2];
    const float* sr_b   = (const float*)d_in[p + 3];
    const float* an_g   = (const float*)d_in[p + 4];
    const float* an_b   = (const float*)d_in[p + 5];
    const float* qkv_w  = (const float*)d_in[p + 6];
    const float* proj_w = (const float*)d_in[p + 7];
    const float* proj_b = (const float*)d_in[p + 8];
    const float* n2_g   = (const float*)d_in[p + 9];
    const float* n2_b   = (const float*)d_in[p + 10];
    const float* fc1_w  = (const float*)d_in[p + 11];
    const float* fc1_b  = (const float*)d_in[p + 12];
    const float* dw_w   = (const float*)d_in[p + 13];
    const float* dw_b   = (const float*)d_in[p + 14];
    const float* fc2_w  = (const float*)d_in[p + 15];
    const float* fc2_b  = (const float*)d_in[p + 16];
    const float* ca_w1  = (const float*)d_in[p + 17];
    const float* ca_w2  = (const float*)d_in[p + 18];
    const float* sp_w   = (const float*)d_in[p + 19];
    const float* sp_b   = (const float*)d_in[p + 20];
    float* out = (float*)d_out;

    float *pxn, *pb1, *pb2;
    __nv_bfloat16 *pqkv16, *pa16, *ph16a, *ph16b, *pw16;
    cudaGetSymbolAddress((void**)&pxn,    g_xn);
    cudaGetSymbolAddress((void**)&pb1,    g_b1);
    cudaGetSymbolAddress((void**)&pb2,    g_b2);
    cudaGetSymbolAddress((void**)&pqkv16, g_qkv16);
    cudaGetSymbolAddress((void**)&pa16,   g_a16);
    cudaGetSymbolAddress((void**)&ph16a,  g_h16a);
    cudaGetSymbolAddress((void**)&ph16b,  g_h16b);
    cudaGetSymbolAddress((void**)&pw16,   g_w16);

    const int TPB = 256;
    const int GEMM_SMEM = NSTAGE * SSTG * 2;   // 98304 bytes
    cudaFuncSetAttribute(gemm_bf16<float>, cudaFuncAttributeMaxDynamicSharedMemorySize,
                         GEMM_SMEM);
    cudaFuncSetAttribute(gemm_bf16<__nv_bfloat16>, cudaFuncAttributeMaxDynamicSharedMemorySize,
                         GEMM_SMEM);

    // 0. bf16 weight conversion (one kernel)
    f2bf_all<<<(393216 + TPB - 1) / TPB, TPB>>>(qkv_w, proj_w, fc1_w, fc2_w, pw16);

    // 1. xn = LN1(x)
    ln256<float><<<ROWS_ * 32 / TPB, TPB>>>(x, pxn, n1_g, n1_b);
    // 2+3. xa16 = bf16(xn + gelu(LN_act(dwconv3(xn))))  (smem-tiled fused)
    {
        dim3 g(16, 16, B_);
        sr_fuse_v2<<<g, TPB>>>(pxn, pa16, sr_w, sr_b, an_g, an_b);
    }
    // 4. qkv = xa @ qkv_w^T  (bf16 out)
    {
        dim3 g(3 * C_ / 128, ROWS_ / 128);
        gemm_bf16<__nv_bfloat16><<<g, TPB, GEMM_SMEM>>>(pa16, pw16 + W16_QKV, pqkv16,
                                                        ROWS_, 3 * C_, C_, nullptr, nullptr, nullptr);
    }
    // 5. q column-softmax stats
    {
        dim3 g(B_, 64);
        qsoft_part<<<g, TPB>>>(pqkv16);
        qsoft_comb<<<(B_ * C_ + TPB - 1) / TPB, TPB>>>();
    }
    // 6. ctx = softmax_d(k)^T v
    {
        dim3 g(16, HEADS_, B_);
        ctx_kernel<<<g, TPB>>>(pqkv16);
        ctx_comb<<<(B_ * HEADS_ * D_ * D_ + TPB - 1) / TPB, TPB>>>();
    }
    // 7. attn = softmax_N(q) @ ctx -> a16 (bf16)
    {
        dim3 g(N_ / 64, B_);
        attn2<<<g, TPB>>>(pqkv16, pa16);
    }
    // 8. x2 = x + attn @ proj_w^T + proj_b + xn -> b1
    {
        dim3 g(C_ / 128, ROWS_ / 128);
        gemm_bf16<float><<<g, TPB, GEMM_SMEM>>>(pa16, pw16 + W16_PROJ, pb1,
                                                ROWS_, C_, C_, proj_b, x, pxn);
    }
    // 9. ln2(x2) -> a16 (bf16)
    ln256<__nv_bfloat16><<<ROWS_ * 32 / TPB, TPB>>>(pb1, pa16, n2_g, n2_b);
    // 10. fc1 -> h16a (bf16)
    {
        dim3 g(HID_ / 128, ROWS_ / 128);
        gemm_bf16<__nv_bfloat16><<<g, TPB, GEMM_SMEM>>>(pa16, pw16 + W16_FC1, ph16a,
                                                        ROWS_, HID_, C_, fc1_b, nullptr, nullptr);
    }
    // 11. dwconv + gelu (bf16, sliding window) -> h16b
    {
        dim3 g(HID_ / 4 / 16, 64, B_);
        dwconv3_bf16_v2<<<g, TPB>>>(ph16a, ph16b, dw_w, dw_b);
    }
    // 12. x3 = x2 + gelu_dw @ fc2_w^T + fc2_b -> b2
    {
        dim3 g(C_ / 128, ROWS_ / 128);
        gemm_bf16<float><<<g, TPB, GEMM_SMEM>>>(ph16b, pw16 + W16_FC2, pb2,
                                                ROWS_, C_, HID_, fc2_b, pb1, nullptr);
    }
    // 13. channel pools
    {
        dim3 g(B_, 64);
        cpool_part<<<g, TPB>>>(pb2);
        cpool_comb<<<(B_ * C_ + TPB - 1) / TPB, TPB>>>();
    }
    // 14. channel attention MLP
    ca_mlp<<<B_, TPB>>>(ca_w1, ca_w2);
    // 15. spatial pools of x3*ca
    spool<<<ROWS_ * 32 / TPB, TPB>>>(pb2);
    // 16. 7x7 spatial conv -> sa
    conv7<<<(ROWS_ + TPB - 1) / TPB, TPB>>>(sp_w, sp_b);
    // 17. out = x3 * ca * sa
    final_scale<<<(ROWS_ * 64 + TPB - 1) / TPB, TPB>>>(pb2, out);
}